// round 6
// baseline (speedup 1.0000x reference)
#include <cuda_runtime.h>
#include <cuda_bf16.h>
#include <cstdint>
#include <math.h>

#define NN 100000
#define NE 600000
#define NG 512
#define HD 128
#define EF 256
#define NCONV 3

// ---- scratch (device globals) ----
__device__ float g_x[NN * HD];
__device__ __nv_bfloat16 g_xh[NN * HD];
__device__ __nv_bfloat16 g_xl[NN * HD];
__device__ __nv_bfloat16 g_Ah[NN * EF];
__device__ __nv_bfloat16 g_Al[NN * EF];
__device__ float g_sG[NN * HD];
__device__ float g_M[NN * HD];
__device__ float g_agg[NN * HD];
__device__ float g_y[NG * HD];
// weight scratch: per conv [We1|Wg] concat [384][128], then We2T [128][256], then WpT
#define WCAT(c) ((c) * 49152)
#define WE2T(c) (147456 + (c) * 32768)
#define WPT 245760
__device__ __nv_bfloat16 g_Wth[262144];
__device__ __nv_bfloat16 g_Wtl[262144];

__device__ __forceinline__ float sp_(float x) {
    return fmaxf(x, 0.f) + log1pf(expf(-fabsf(x)));
}
__device__ __forceinline__ float sigm_(float x) {
    return 1.f / (1.f + expf(-x));
}
__device__ __forceinline__ void split_bf(float x, __nv_bfloat16& h, __nv_bfloat16& l) {
    h = __float2bfloat16(x);
    l = __float2bfloat16(x - __bfloat162float(h));
}

__global__ void k_wsplit_all(const float* __restrict__ Wg, const float* __restrict__ We1,
                             const float* __restrict__ We2, const float* __restrict__ Wp) {
    int i = blockIdx.x * blockDim.x + threadIdx.x;
    if (i >= 262144) return;
    float w;
    if (i < 147456) {                          // concat [c][n=384][k=128]
        int c = i / 49152, j = i % 49152;
        int n = j / HD, k = j % HD;
        if (n < EF) w = We1[c * 32768 + k * EF + n];
        else        w = Wg[c * 16384 + k * HD + (n - EF)];
    } else if (i < 245760) {                   // We2T [c][n=128][k=256]
        int j = i - 147456;
        int c = j / 32768, jj = j % 32768;
        int n = jj >> 8, k = jj & 255;
        w = We2[c * 32768 + k * HD + n];
    } else {                                   // WpT [n=128][k=128]
        int j = i - 245760;
        int n = j / HD, k = j % HD;
        w = Wp[k * HD + n];
    }
    __nv_bfloat16 h, l;
    split_bf(w, h, l);
    g_Wth[i] = h;
    g_Wtl[i] = l;
}

__global__ void k_zero() {
    int i = blockIdx.x * blockDim.x + threadIdx.x;
    const int n4 = NN * HD / 4;
    if (i < n4) ((float4*)g_agg)[i] = make_float4(0.f, 0.f, 0.f, 0.f);
    if (i < NG * HD / 4) ((float4*)g_y)[i] = make_float4(0.f, 0.f, 0.f, 0.f);
}

__device__ __forceinline__ void store_split4(int i4, float4 v) {
    __nv_bfloat16 h0, h1, h2, h3, l0, l1, l2, l3;
    split_bf(v.x, h0, l0); split_bf(v.y, h1, l1);
    split_bf(v.z, h2, l2); split_bf(v.w, h3, l3);
    ((__nv_bfloat162*)g_xh)[i4 * 2] = __nv_bfloat162(h0, h1);
    ((__nv_bfloat162*)g_xh)[i4 * 2 + 1] = __nv_bfloat162(h2, h3);
    ((__nv_bfloat162*)g_xl)[i4 * 2] = __nv_bfloat162(l0, l1);
    ((__nv_bfloat162*)g_xl)[i4 * 2 + 1] = __nv_bfloat162(l2, l3);
}

__global__ void k_embed(const int* __restrict__ nodes, const float* __restrict__ embed) {
    int i = blockIdx.x * blockDim.x + threadIdx.x;
    if (i >= NN * (HD / 4)) return;
    int node = nodes[i >> 5];
    float4 v = ((const float4*)embed)[node * 32 + (i & 31)];
    ((float4*)g_x)[i] = v;
    store_split4(i, v);
}

// ======================================================================
// bf16 split-3 MMA GEMM. 3-stage cp.async, 1 barrier/k-tile,
// whole-k-tile fragment burst. Block 128x64x32, 8 warps.
// EPI: 1 split(softplus)->Ch/Cl ; 2 Gb*softplus->C ; 3 atomicAdd C[gidx];
//      4 merged: n<256 -> EPI1 (stride 256), n>=256 -> sigmoid->C (stride 128)
// ======================================================================
#define LDA 40

__device__ __forceinline__ void cp16(uint32_t dst, const void* src, bool pred) {
    int sz = pred ? 16 : 0;
    asm volatile("cp.async.cg.shared.global [%0], [%1], 16, %2;"
                 :: "r"(dst), "l"(src), "r"(sz));
}
__device__ __forceinline__ void cp_commit() {
    asm volatile("cp.async.commit_group;");
}
template <int N_>
__device__ __forceinline__ void cp_wait() {
    asm volatile("cp.async.wait_group %0;" :: "n"(N_));
}
__device__ __forceinline__ void ldm_x4(uint32_t addr, uint32_t r[4]) {
    asm volatile("ldmatrix.sync.aligned.m8n8.x4.shared.b16 {%0,%1,%2,%3},[%4];"
                 : "=r"(r[0]), "=r"(r[1]), "=r"(r[2]), "=r"(r[3]) : "r"(addr));
}
__device__ __forceinline__ void mma16816(float c[4], const uint32_t a[4],
                                         uint32_t b0, uint32_t b1) {
    asm volatile(
        "mma.sync.aligned.m16n8k16.row.col.f32.bf16.bf16.f32 "
        "{%0,%1,%2,%3},{%4,%5,%6,%7},{%8,%9},{%0,%1,%2,%3};"
        : "+f"(c[0]), "+f"(c[1]), "+f"(c[2]), "+f"(c[3])
        : "r"(a[0]), "r"(a[1]), "r"(a[2]), "r"(a[3]), "r"(b0), "r"(b1));
}

template <int EPI, int NT_, int KT_>
__global__ void __launch_bounds__(256, 2) k_gemm_bf(
    const __nv_bfloat16* __restrict__ Ah, const __nv_bfloat16* __restrict__ Al,
    const __nv_bfloat16* __restrict__ Bh, const __nv_bfloat16* __restrict__ Bl,
    float* __restrict__ C, const float* __restrict__ Gb, const int* __restrict__ gidx,
    __nv_bfloat16* __restrict__ Ch, __nv_bfloat16* __restrict__ Cl,
    int M) {
    constexpr int N = NT_;
    constexpr int K = KT_;
    constexpr int T = K / 32;

    __shared__ __nv_bfloat16 sA[3][2][128 * LDA];
    __shared__ __nv_bfloat16 sB[3][2][64 * LDA];

    const int tid = threadIdx.x;
    const int lane = tid & 31;
    const int warp = tid >> 5;
    const int wm = warp >> 1;
    const int wn = warp & 1;
    const int m0 = blockIdx.y * 128;
    const int n0 = blockIdx.x * 64;

    float acc[2][4][4];
#pragma unroll
    for (int i = 0; i < 2; i++)
#pragma unroll
        for (int j = 0; j < 4; j++)
#pragma unroll
            for (int q = 0; q < 4; q++) acc[i][j][q] = 0.f;

    uint32_t aB[3][2], bB[3][2];
#pragma unroll
    for (int st = 0; st < 3; st++)
#pragma unroll
        for (int hl = 0; hl < 2; hl++) {
            aB[st][hl] = (uint32_t)__cvta_generic_to_shared(&sA[st][hl][0]);
            bB[st][hl] = (uint32_t)__cvta_generic_to_shared(&sB[st][hl][0]);
        }

    const int a_r0 = tid >> 2;
    const int a_kc = (tid & 3) * 8;
    const int b_r = tid >> 2;
    const int b_kc = (tid & 3) * 8;

    const int a_row = ((lane >> 3) & 1) * 8 + (lane & 7);
    const int a_kof = (lane >> 4) * 8;
    const int b_row = ((lane >> 4) & 1) * 8 + (lane & 7);
    const int b_kof = ((lane >> 3) & 1) * 8;

    const bool pA0 = (m0 + a_r0) < M;
    const bool pA1 = (m0 + a_r0 + 64) < M;
    const uint32_t aOff0 = (uint32_t)(a_r0 * LDA + a_kc) * 2u;
    const uint32_t aOff1 = (uint32_t)((a_r0 + 64) * LDA + a_kc) * 2u;
    const uint32_t bOff = (uint32_t)(b_r * LDA + b_kc) * 2u;
    const __nv_bfloat16* gAh0 = Ah + (pA0 ? (long)(m0 + a_r0) * K + a_kc : 0);
    const __nv_bfloat16* gAl0 = Al + (pA0 ? (long)(m0 + a_r0) * K + a_kc : 0);
    const __nv_bfloat16* gAh1 = Ah + (pA1 ? (long)(m0 + a_r0 + 64) * K + a_kc : 0);
    const __nv_bfloat16* gAl1 = Al + (pA1 ? (long)(m0 + a_r0 + 64) * K + a_kc : 0);
    const __nv_bfloat16* gBh = Bh + (long)(n0 + b_r) * K + b_kc;
    const __nv_bfloat16* gBl = Bl + (long)(n0 + b_r) * K + b_kc;

#define LOAD_STAGE(st, k0)                          \
    do {                                            \
        cp16(aB[st][0] + aOff0, gAh0 + (k0), pA0);  \
        cp16(aB[st][1] + aOff0, gAl0 + (k0), pA0);  \
        cp16(aB[st][0] + aOff1, gAh1 + (k0), pA1);  \
        cp16(aB[st][1] + aOff1, gAl1 + (k0), pA1);  \
        cp16(bB[st][0] + bOff, gBh + (k0), true);   \
        cp16(bB[st][1] + bOff, gBl + (k0), true);   \
    } while (0)

    LOAD_STAGE(0, 0);
    cp_commit();
    LOAD_STAGE(1, 32);
    cp_commit();

#pragma unroll
    for (int kt = 0; kt < T; kt++) {
        const int st = kt % 3;
        cp_wait<1>();
        __syncthreads();

        // burst-load ALL fragments for this k-tile (both ks halves)
        uint32_t fah[2][2][4], fal[2][2][4], fbh[2][2][4], fbl[2][2][4];
#pragma unroll
        for (int ks2 = 0; ks2 < 2; ks2++) {
#pragma unroll
            for (int mt = 0; mt < 2; mt++) {
                uint32_t off =
                    (uint32_t)((wm * 32 + mt * 16 + a_row) * LDA + ks2 * 16 + a_kof) * 2u;
                ldm_x4(aB[st][0] + off, fah[ks2][mt]);
                ldm_x4(aB[st][1] + off, fal[ks2][mt]);
            }
#pragma unroll
            for (int np = 0; np < 2; np++) {
                uint32_t off =
                    (uint32_t)((wn * 32 + np * 16 + b_row) * LDA + ks2 * 16 + b_kof) * 2u;
                ldm_x4(bB[st][0] + off, fbh[ks2][np]);
                ldm_x4(bB[st][1] + off, fbl[ks2][np]);
            }
        }

        // prefetch stage kt+2 (slot (kt+2)%3 != st, != (kt+1)%3)
        if (kt + 2 < T) LOAD_STAGE((kt + 2) % 3, (kt + 2) * 32);
        cp_commit();

        // 48 MMAs, term-major: max distance between acc reuse
#pragma unroll
        for (int term = 0; term < 3; term++) {
#pragma unroll
            for (int ks2 = 0; ks2 < 2; ks2++) {
#pragma unroll
                for (int mt = 0; mt < 2; mt++) {
#pragma unroll
                    for (int nt = 0; nt < 4; nt++) {
                        uint32_t b0, b1;
                        const uint32_t* fa;
                        if (term == 0) {
                            fa = fah[ks2][mt];
                            b0 = fbh[ks2][nt >> 1][(nt & 1) * 2];
                            b1 = fbh[ks2][nt >> 1][(nt & 1) * 2 + 1];
                        } else if (term == 1) {
                            fa = fah[ks2][mt];
                            b0 = fbl[ks2][nt >> 1][(nt & 1) * 2];
                            b1 = fbl[ks2][nt >> 1][(nt & 1) * 2 + 1];
                        } else {
                            fa = fal[ks2][mt];
                            b0 = fbh[ks2][nt >> 1][(nt & 1) * 2];
                            b1 = fbh[ks2][nt >> 1][(nt & 1) * 2 + 1];
                        }
                        mma16816(acc[mt][nt], fa, b0, b1);
                    }
                }
            }
        }
    }
#undef LOAD_STAGE

    // epilogue
#pragma unroll
    for (int mt = 0; mt < 2; mt++) {
#pragma unroll
        for (int nt = 0; nt < 4; nt++) {
            int rbase = m0 + wm * 32 + mt * 16 + (lane >> 2);
            int col = n0 + wn * 32 + nt * 8 + (lane & 3) * 2;
            float* c = acc[mt][nt];
#pragma unroll
            for (int half = 0; half < 2; half++) {
                int row = rbase + half * 8;
                if (row >= M) continue;
                float v0 = c[half * 2], v1 = c[half * 2 + 1];
                if (EPI == 1 || (EPI == 4 && n0 < 256)) {
                    long base = (long)row * 256 + col;  // A store, N=256
                    __nv_bfloat16 h0, h1, l0, l1;
                    split_bf(sp_(v0), h0, l0);
                    split_bf(sp_(v1), h1, l1);
                    *reinterpret_cast<__nv_bfloat162*>(&Ch[base]) = __nv_bfloat162(h0, h1);
                    *reinterpret_cast<__nv_bfloat162*>(&Cl[base]) = __nv_bfloat162(l0, l1);
                } else if (EPI == 4) {
                    long base = (long)row * HD + (col - 256);  // gate store
                    *reinterpret_cast<float2*>(&C[base]) = make_float2(sigm_(v0), sigm_(v1));
                } else if (EPI == 2) {
                    long base = (long)row * N + col;
                    float2 g2 = *reinterpret_cast<const float2*>(&Gb[base]);
                    *reinterpret_cast<float2*>(&C[base]) =
                        make_float2(g2.x * sp_(v0), g2.y * sp_(v1));
                } else {
                    int seg = gidx[row];
                    atomicAdd(reinterpret_cast<float2*>(&C[(long)seg * N + col]),
                              make_float2(v0, v1));
                }
            }
        }
    }
}

// ---- edge scatter with float4 vector atomics ----
__global__ void k_scatter(const int* __restrict__ src, const int* __restrict__ tgt) {
    long i = (long)blockIdx.x * blockDim.x + threadIdx.x;
    if (i >= (long)NE * (HD / 4)) return;
    int e = (int)(i >> 5);
    int c = (int)(i & 31);
    int s = src[e], t = tgt[e];
    float4 v = ((const float4*)g_M)[(long)s * 32 + c];
    atomicAdd(reinterpret_cast<float4*>(&g_agg[(long)t * HD + c * 4]), v);
}

__global__ void k_update() {
    int i = blockIdx.x * blockDim.x + threadIdx.x;
    if (i >= NN * (HD / 4)) return;
    float4 a = ((float4*)g_agg)[i];
    float4 x = ((float4*)g_x)[i];
    x.x += sp_(a.x);
    x.y += sp_(a.y);
    x.z += sp_(a.z);
    x.w += sp_(a.w);
    ((float4*)g_x)[i] = x;
    store_split4(i, x);
    ((float4*)g_agg)[i] = make_float4(0.f, 0.f, 0.f, 0.f);
}

__global__ void k_mlp(const float* __restrict__ counts,
                      const float* __restrict__ Wfc1, const float* __restrict__ bfc1,
                      const float* __restrict__ Wfc2, const float* __restrict__ bfc2,
                      const float* __restrict__ Wr, const float* __restrict__ br,
                      float* __restrict__ out) {
    __shared__ float s0[HD];
    __shared__ float s1[HD];
    __shared__ float red[HD];
    int g = blockIdx.x, t = threadIdx.x;

    float yv = g_y[g * HD + t] / counts[g];
    s0[t] = sp_(yv);
    __syncthreads();

    float acc = bfc1[t];
#pragma unroll 8
    for (int k = 0; k < HD; k++) acc += s0[k] * Wfc1[k * HD + t];
    s1[t] = sp_(acc);
    __syncthreads();

    acc = bfc2[t];
#pragma unroll 8
    for (int k = 0; k < HD; k++) acc += s1[k] * Wfc2[k * HD + t];
    float h2 = sp_(acc);

    red[t] = h2 * Wr[t];
    __syncthreads();
    for (int s = HD / 2; s > 0; s >>= 1) {
        if (t < s) red[t] += red[t + s];
        __syncthreads();
    }
    if (t == 0) out[g] = red[0] + br[0];
}

extern "C" void kernel_launch(void* const* d_in, const int* in_sizes, int n_in,
                              void* d_out, int out_size) {
    const int* nodes = (const int*)d_in[0];
    const int* esrc = (const int*)d_in[1];
    const int* etgt = (const int*)d_in[2];
    const int* gidx = (const int*)d_in[3];
    const float* counts = (const float*)d_in[4];
    const float* embed = (const float*)d_in[5];
    const float* Wg = (const float*)d_in[6];
    const float* We1 = (const float*)d_in[7];
    const float* We2 = (const float*)d_in[8];
    const float* Wp = (const float*)d_in[9];
    const float* Wfc1 = (const float*)d_in[10];
    const float* bfc1 = (const float*)d_in[11];
    const float* Wfc2 = (const float*)d_in[12];
    const float* bfc2 = (const float*)d_in[13];
    const float* Wr = (const float*)d_in[14];
    const float* br = (const float*)d_in[15];
    float* out = (float*)d_out;

    __nv_bfloat16 *pxh, *pxl, *pAh, *pAl, *pWth, *pWtl;
    float *psG, *pM, *py;
    cudaGetSymbolAddress((void**)&pxh, g_xh);
    cudaGetSymbolAddress((void**)&pxl, g_xl);
    cudaGetSymbolAddress((void**)&pAh, g_Ah);
    cudaGetSymbolAddress((void**)&pAl, g_Al);
    cudaGetSymbolAddress((void**)&pWth, g_Wth);
    cudaGetSymbolAddress((void**)&pWtl, g_Wtl);
    cudaGetSymbolAddress((void**)&psG, g_sG);
    cudaGetSymbolAddress((void**)&pM, g_M);
    cudaGetSymbolAddress((void**)&py, g_y);

    const int blocksM = (NN + 127) / 128;

    k_wsplit_all<<<(262144 + 255) / 256, 256>>>(Wg, We1, We2, Wp);
    {
        int n = NN * HD / 4;
        k_zero<<<(n + 255) / 256, 256>>>();
    }
    {
        int n = NN * (HD / 4);
        k_embed<<<(n + 255) / 256, 256>>>(nodes, embed);
    }
    for (int i = 0; i < NCONV; i++) {
        // merged: sp(x@We1) -> Ah/Al  AND  sigmoid(x@Wg) -> sG
        k_gemm_bf<4, 384, HD><<<dim3(384 / 64, blocksM), 256>>>(
            pxh, pxl, pWth + WCAT(i), pWtl + WCAT(i),
            psG, nullptr, nullptr, pAh, pAl, NN);
        // M = sG * sp(A @ We2)
        k_gemm_bf<2, HD, EF><<<dim3(HD / 64, blocksM), 256>>>(
            pAh, pAl, pWth + WE2T(i), pWtl + WE2T(i),
            pM, psG, nullptr, nullptr, nullptr, NN);
        {
            long n = (long)NE * (HD / 4);
            k_scatter<<<(int)((n + 255) / 256), 256>>>(esrc, etgt);
        }
        {
            int n = NN * (HD / 4);
            k_update<<<(n + 255) / 256, 256>>>();
        }
    }
    k_gemm_bf<3, HD, HD><<<dim3(HD / 64, blocksM), 256>>>(
        pxh, pxl, pWth + WPT, pWtl + WPT,
        py, nullptr, gidx, nullptr, nullptr, NN);
    k_mlp<<<NG, HD>>>(counts, Wfc1, bfc1, Wfc2, bfc2, Wr, br, out);
}

// round 8
// speedup vs baseline: 1.0963x; 1.0963x over previous
#include <cuda_runtime.h>
#include <cuda_bf16.h>
#include <cstdint>
#include <math.h>

#define NN 100000
#define NE 600000
#define NG 512
#define HD 128
#define EF 256
#define NCONV 3

// ---- scratch (device globals) ----
__device__ float g_x[NN * HD];
__device__ __nv_bfloat16 g_xh[NN * HD];
__device__ __nv_bfloat16 g_xl[NN * HD];
__device__ __nv_bfloat16 g_Ah[NN * EF];
__device__ __nv_bfloat16 g_Al[NN * EF];
__device__ float g_sG[NN * HD];
__device__ float g_M[NN * HD];
__device__ float g_agg[NN * HD];
__device__ float g_y[NG * HD];
// weight scratch: per conv [We1|Wg] concat [384][128], then We2T, then WpT
#define WCAT(c) ((c) * 49152)
#define WE2T(c) (147456 + (c) * 32768)
#define WPT 245760
__device__ __nv_bfloat16 g_Wth[262144];
__device__ __nv_bfloat16 g_Wtl[262144];

// fast softplus / sigmoid (MUFU ex2/lg2; abs err ~1e-6, tolerance 1e-3)
__device__ __forceinline__ float sp_(float x) {
    return fmaxf(x, 0.f) + __logf(1.f + __expf(-fabsf(x)));
}
__device__ __forceinline__ float sigm_(float x) {
    return 1.f / (1.f + __expf(-x));
}
__device__ __forceinline__ void split_bf(float x, __nv_bfloat16& h, __nv_bfloat16& l) {
    h = __float2bfloat16(x);
    l = __float2bfloat16(x - __bfloat162float(h));
}

__global__ void k_wsplit_all(const float* __restrict__ Wg, const float* __restrict__ We1,
                             const float* __restrict__ We2, const float* __restrict__ Wp) {
    int i = blockIdx.x * blockDim.x + threadIdx.x;
    if (i >= 262144) return;
    float w;
    if (i < 147456) {                          // concat [c][n=384][k=128]
        int c = i / 49152, j = i % 49152;
        int n = j / HD, k = j % HD;
        if (n < EF) w = We1[c * 32768 + k * EF + n];
        else        w = Wg[c * 16384 + k * HD + (n - EF)];
    } else if (i < 245760) {                   // We2T [c][n=128][k=256]
        int j = i - 147456;
        int c = j / 32768, jj = j % 32768;
        int n = jj >> 8, k = jj & 255;
        w = We2[c * 32768 + k * HD + n];
    } else {                                   // WpT [n=128][k=128]
        int j = i - 245760;
        int n = j / HD, k = j % HD;
        w = Wp[k * HD + n];
    }
    __nv_bfloat16 h, l;
    split_bf(w, h, l);
    g_Wth[i] = h;
    g_Wtl[i] = l;
}

// zero y only (agg is zero at module load and re-zeroed by k_update every call)
__global__ void k_zero_y() {
    int i = blockIdx.x * blockDim.x + threadIdx.x;
    if (i < NG * HD / 4) ((float4*)g_y)[i] = make_float4(0.f, 0.f, 0.f, 0.f);
}

__device__ __forceinline__ void store_split4(int i4, float4 v) {
    __nv_bfloat16 h0, h1, h2, h3, l0, l1, l2, l3;
    split_bf(v.x, h0, l0); split_bf(v.y, h1, l1);
    split_bf(v.z, h2, l2); split_bf(v.w, h3, l3);
    ((__nv_bfloat162*)g_xh)[i4 * 2] = __nv_bfloat162(h0, h1);
    ((__nv_bfloat162*)g_xh)[i4 * 2 + 1] = __nv_bfloat162(h2, h3);
    ((__nv_bfloat162*)g_xl)[i4 * 2] = __nv_bfloat162(l0, l1);
    ((__nv_bfloat162*)g_xl)[i4 * 2 + 1] = __nv_bfloat162(l2, l3);
}

__global__ void k_embed(const int* __restrict__ nodes, const float* __restrict__ embed) {
    int i = blockIdx.x * blockDim.x + threadIdx.x;
    if (i >= NN * (HD / 4)) return;
    int node = nodes[i >> 5];
    float4 v = ((const float4*)embed)[node * 32 + (i & 31)];
    ((float4*)g_x)[i] = v;
    store_split4(i, v);
}

// ======================================================================
// bf16 split-3 MMA GEMM, compile-time N/K, 2-stage cp.async (R5 pipeline).
// A: hi/lo bf16 [M,K].  B: hi/lo bf16 [N,K].  Block 128x64x32, 8 warps.
// EPI: 2 Gb*softplus->C ; 3 atomicAdd C[gidx] ;
//      4 merged: n<256 -> split(softplus)->Ch/Cl (stride 256),
//                n>=256 -> sigmoid->C (stride 128)
// ======================================================================
#define LDA 40

__device__ __forceinline__ void cp16(uint32_t dst, const void* src, bool pred) {
    int sz = pred ? 16 : 0;
    asm volatile("cp.async.cg.shared.global [%0], [%1], 16, %2;"
                 :: "r"(dst), "l"(src), "r"(sz));
}
__device__ __forceinline__ void cp_commit() {
    asm volatile("cp.async.commit_group;");
}
template <int N_>
__device__ __forceinline__ void cp_wait() {
    asm volatile("cp.async.wait_group %0;" :: "n"(N_));
}
__device__ __forceinline__ void ldm_x4(uint32_t addr, uint32_t r[4]) {
    asm volatile("ldmatrix.sync.aligned.m8n8.x4.shared.b16 {%0,%1,%2,%3},[%4];"
                 : "=r"(r[0]), "=r"(r[1]), "=r"(r[2]), "=r"(r[3]) : "r"(addr));
}
__device__ __forceinline__ void mma16816(float c[4], const uint32_t a[4],
                                         uint32_t b0, uint32_t b1) {
    asm volatile(
        "mma.sync.aligned.m16n8k16.row.col.f32.bf16.bf16.f32 "
        "{%0,%1,%2,%3},{%4,%5,%6,%7},{%8,%9},{%0,%1,%2,%3};"
        : "+f"(c[0]), "+f"(c[1]), "+f"(c[2]), "+f"(c[3])
        : "r"(a[0]), "r"(a[1]), "r"(a[2]), "r"(a[3]), "r"(b0), "r"(b1));
}

template <int EPI, int NT_, int KT_>
__global__ void __launch_bounds__(256) k_gemm_bf(
    const __nv_bfloat16* __restrict__ Ah, const __nv_bfloat16* __restrict__ Al,
    const __nv_bfloat16* __restrict__ Bh, const __nv_bfloat16* __restrict__ Bl,
    float* __restrict__ C, const float* __restrict__ Gb, const int* __restrict__ gidx,
    __nv_bfloat16* __restrict__ Ch, __nv_bfloat16* __restrict__ Cl,
    int M) {
    constexpr int N = NT_;
    constexpr int K = KT_;
    constexpr int T = K / 32;

    __shared__ __nv_bfloat16 sA[2][2][128 * LDA];
    __shared__ __nv_bfloat16 sB[2][2][64 * LDA];

    const int tid = threadIdx.x;
    const int lane = tid & 31;
    const int warp = tid >> 5;
    const int wm = warp >> 1;
    const int wn = warp & 1;
    const int m0 = blockIdx.y * 128;
    const int n0 = blockIdx.x * 64;

    float acc[2][4][4];
#pragma unroll
    for (int i = 0; i < 2; i++)
#pragma unroll
        for (int j = 0; j < 4; j++)
#pragma unroll
            for (int q = 0; q < 4; q++) acc[i][j][q] = 0.f;

    uint32_t aB[2][2], bB[2][2];
#pragma unroll
    for (int st = 0; st < 2; st++)
#pragma unroll
        for (int hl = 0; hl < 2; hl++) {
            aB[st][hl] = (uint32_t)__cvta_generic_to_shared(&sA[st][hl][0]);
            bB[st][hl] = (uint32_t)__cvta_generic_to_shared(&sB[st][hl][0]);
        }

    const int a_r0 = tid >> 2;
    const int a_kc = (tid & 3) * 8;
    const int b_r = tid >> 2;
    const int b_kc = (tid & 3) * 8;

    const int a_row = ((lane >> 3) & 1) * 8 + (lane & 7);
    const int a_kof = (lane >> 4) * 8;
    const int b_row = ((lane >> 4) & 1) * 8 + (lane & 7);
    const int b_kof = ((lane >> 3) & 1) * 8;

    const bool pA0 = (m0 + a_r0) < M;
    const bool pA1 = (m0 + a_r0 + 64) < M;
    const uint32_t aOff0 = (uint32_t)(a_r0 * LDA + a_kc) * 2u;
    const uint32_t aOff1 = (uint32_t)((a_r0 + 64) * LDA + a_kc) * 2u;
    const uint32_t bOff = (uint32_t)(b_r * LDA + b_kc) * 2u;
    const __nv_bfloat16* gAh0 = Ah + (pA0 ? (long)(m0 + a_r0) * K + a_kc : 0);
    const __nv_bfloat16* gAl0 = Al + (pA0 ? (long)(m0 + a_r0) * K + a_kc : 0);
    const __nv_bfloat16* gAh1 = Ah + (pA1 ? (long)(m0 + a_r0 + 64) * K + a_kc : 0);
    const __nv_bfloat16* gAl1 = Al + (pA1 ? (long)(m0 + a_r0 + 64) * K + a_kc : 0);
    const __nv_bfloat16* gBh = Bh + (long)(n0 + b_r) * K + b_kc;
    const __nv_bfloat16* gBl = Bl + (long)(n0 + b_r) * K + b_kc;

#define LOAD_STAGE(st, k0)                                   \
    do {                                                     \
        cp16(aB[st][0] + aOff0, gAh0 + (k0), pA0);           \
        cp16(aB[st][1] + aOff0, gAl0 + (k0), pA0);           \
        cp16(aB[st][0] + aOff1, gAh1 + (k0), pA1);           \
        cp16(aB[st][1] + aOff1, gAl1 + (k0), pA1);           \
        cp16(bB[st][0] + bOff, gBh + (k0), true);            \
        cp16(bB[st][1] + bOff, gBl + (k0), true);            \
        cp_commit();                                         \
    } while (0)

    LOAD_STAGE(0, 0);

#pragma unroll
    for (int kt = 0; kt < T; kt++) {
        if (kt + 1 < T) {
            LOAD_STAGE((kt + 1) & 1, (kt + 1) * 32);
            cp_wait<1>();
        } else {
            cp_wait<0>();
        }
        __syncthreads();

        const int st = kt & 1;
#pragma unroll
        for (int ks = 0; ks < 32; ks += 16) {
            uint32_t fah[2][4], fal[2][4], fbh[2][4], fbl[2][4];
#pragma unroll
            for (int mt = 0; mt < 2; mt++) {
                uint32_t off = (uint32_t)((wm * 32 + mt * 16 + a_row) * LDA + ks + a_kof) * 2u;
                ldm_x4(aB[st][0] + off, fah[mt]);
                ldm_x4(aB[st][1] + off, fal[mt]);
            }
#pragma unroll
            for (int np = 0; np < 2; np++) {
                uint32_t off = (uint32_t)((wn * 32 + np * 16 + b_row) * LDA + ks + b_kof) * 2u;
                ldm_x4(bB[st][0] + off, fbh[np]);
                ldm_x4(bB[st][1] + off, fbl[np]);
            }
#pragma unroll
            for (int term = 0; term < 3; term++) {
#pragma unroll
                for (int mt = 0; mt < 2; mt++) {
#pragma unroll
                    for (int nt = 0; nt < 4; nt++) {
                        uint32_t b0, b1;
                        const uint32_t* fa;
                        if (term == 0) {
                            fa = fah[mt];
                            b0 = fbh[nt >> 1][(nt & 1) * 2];
                            b1 = fbh[nt >> 1][(nt & 1) * 2 + 1];
                        } else if (term == 1) {
                            fa = fah[mt];
                            b0 = fbl[nt >> 1][(nt & 1) * 2];
                            b1 = fbl[nt >> 1][(nt & 1) * 2 + 1];
                        } else {
                            fa = fal[mt];
                            b0 = fbh[nt >> 1][(nt & 1) * 2];
                            b1 = fbh[nt >> 1][(nt & 1) * 2 + 1];
                        }
                        mma16816(acc[mt][nt], fa, b0, b1);
                    }
                }
            }
        }
        __syncthreads();
    }
#undef LOAD_STAGE

    // epilogue
#pragma unroll
    for (int mt = 0; mt < 2; mt++) {
#pragma unroll
        for (int nt = 0; nt < 4; nt++) {
            int rbase = m0 + wm * 32 + mt * 16 + (lane >> 2);
            int col = n0 + wn * 32 + nt * 8 + (lane & 3) * 2;
            float* c = acc[mt][nt];
#pragma unroll
            for (int half = 0; half < 2; half++) {
                int row = rbase + half * 8;
                if (row >= M) continue;
                float v0 = c[half * 2], v1 = c[half * 2 + 1];
                if (EPI == 4 && n0 < 256) {
                    long base = (long)row * 256 + col;   // A store, N=256 region
                    __nv_bfloat16 h0, h1, l0, l1;
                    split_bf(sp_(v0), h0, l0);
                    split_bf(sp_(v1), h1, l1);
                    *reinterpret_cast<__nv_bfloat162*>(&Ch[base]) = __nv_bfloat162(h0, h1);
                    *reinterpret_cast<__nv_bfloat162*>(&Cl[base]) = __nv_bfloat162(l0, l1);
                } else if (EPI == 4) {
                    long base = (long)row * HD + (col - 256);  // gate store
                    *reinterpret_cast<float2*>(&C[base]) = make_float2(sigm_(v0), sigm_(v1));
                } else if (EPI == 2) {
                    long base = (long)row * N + col;
                    float2 g2 = *reinterpret_cast<const float2*>(&Gb[base]);
                    *reinterpret_cast<float2*>(&C[base]) =
                        make_float2(g2.x * sp_(v0), g2.y * sp_(v1));
                } else {  // EPI == 3
                    int seg = gidx[row];
                    atomicAdd(reinterpret_cast<float2*>(&C[(long)seg * N + col]),
                              make_float2(v0, v1));
                }
            }
        }
    }
}

// ---- edge scatter with float4 vector atomics ----
__global__ void k_scatter(const int* __restrict__ src, const int* __restrict__ tgt) {
    long i = (long)blockIdx.x * blockDim.x + threadIdx.x;
    if (i >= (long)NE * (HD / 4)) return;
    int e = (int)(i >> 5);
    int c = (int)(i & 31);
    int s = src[e], t = tgt[e];
    float4 v = ((const float4*)g_M)[(long)s * 32 + c];
    atomicAdd(reinterpret_cast<float4*>(&g_agg[(long)t * HD + c * 4]), v);
}

__global__ void k_update() {
    int i = blockIdx.x * blockDim.x + threadIdx.x;
    if (i >= NN * (HD / 4)) return;
    float4 a = ((float4*)g_agg)[i];
    float4 x = ((float4*)g_x)[i];
    x.x += sp_(a.x);
    x.y += sp_(a.y);
    x.z += sp_(a.z);
    x.w += sp_(a.w);
    ((float4*)g_x)[i] = x;
    store_split4(i, x);
    ((float4*)g_agg)[i] = make_float4(0.f, 0.f, 0.f, 0.f);
}

__global__ void k_mlp(const float* __restrict__ counts,
                      const float* __restrict__ Wfc1, const float* __restrict__ bfc1,
                      const float* __restrict__ Wfc2, const float* __restrict__ bfc2,
                      const float* __restrict__ Wr, const float* __restrict__ br,
                      float* __restrict__ out) {
    __shared__ float s0[HD];
    __shared__ float s1[HD];
    __shared__ float red[HD];
    int g = blockIdx.x, t = threadIdx.x;

    float yv = g_y[g * HD + t] / counts[g];
    s0[t] = sp_(yv);
    __syncthreads();

    float acc = bfc1[t];
#pragma unroll 8
    for (int k = 0; k < HD; k++) acc += s0[k] * Wfc1[k * HD + t];
    s1[t] = sp_(acc);
    __syncthreads();

    acc = bfc2[t];
#pragma unroll 8
    for (int k = 0; k < HD; k++) acc += s1[k] * Wfc2[k * HD + t];
    float h2 = sp_(acc);

    red[t] = h2 * Wr[t];
    __syncthreads();
    for (int s = HD / 2; s > 0; s >>= 1) {
        if (t < s) red[t] += red[t + s];
        __syncthreads();
    }
    if (t == 0) out[g] = red[0] + br[0];
}

extern "C" void kernel_launch(void* const* d_in, const int* in_sizes, int n_in,
                              void* d_out, int out_size) {
    const int* nodes = (const int*)d_in[0];
    const int* esrc = (const int*)d_in[1];
    const int* etgt = (const int*)d_in[2];
    const int* gidx = (const int*)d_in[3];
    const float* counts = (const float*)d_in[4];
    const float* embed = (const float*)d_in[5];
    const float* Wg = (const float*)d_in[6];
    const float* We1 = (const float*)d_in[7];
    const float* We2 = (const float*)d_in[8];
    const float* Wp = (const float*)d_in[9];
    const float* Wfc1 = (const float*)d_in[10];
    const float* bfc1 = (const float*)d_in[11];
    const float* Wfc2 = (const float*)d_in[12];
    const float* bfc2 = (const float*)d_in[13];
    const float* Wr = (const float*)d_in[14];
    const float* br = (const float*)d_in[15];
    float* out = (float*)d_out;

    __nv_bfloat16 *pxh, *pxl, *pAh, *pAl, *pWth, *pWtl;
    float *psG, *pM, *py;
    cudaGetSymbolAddress((void**)&pxh, g_xh);
    cudaGetSymbolAddress((void**)&pxl, g_xl);
    cudaGetSymbolAddress((void**)&pAh, g_Ah);
    cudaGetSymbolAddress((void**)&pAl, g_Al);
    cudaGetSymbolAddress((void**)&pWth, g_Wth);
    cudaGetSymbolAddress((void**)&pWtl, g_Wtl);
    cudaGetSymbolAddress((void**)&psG, g_sG);
    cudaGetSymbolAddress((void**)&pM, g_M);
    cudaGetSymbolAddress((void**)&py, g_y);

    const int blocksM = (NN + 127) / 128;

    k_wsplit_all<<<(262144 + 255) / 256, 256>>>(Wg, We1, We2, Wp);
    k_zero_y<<<(NG * HD / 4 + 255) / 256, 256>>>();
    {
        int n = NN * (HD / 4);
        k_embed<<<(n + 255) / 256, 256>>>(nodes, embed);
    }
    for (int i = 0; i < NCONV; i++) {
        // merged: sp(x@We1) -> Ah/Al (n-tiles 0..3) AND sigmoid(x@Wg) -> sG (n-tiles 4,5)
        k_gemm_bf<4, 384, HD><<<dim3(384 / 64, blocksM), 256>>>(
            pxh, pxl, pWth + WCAT(i), pWtl + WCAT(i),
            psG, nullptr, nullptr, pAh, pAl, NN);
        // M = sG * sp(A @ We2)
        k_gemm_bf<2, HD, EF><<<dim3(HD / 64, blocksM), 256>>>(
            pAh, pAl, pWth + WE2T(i), pWtl + WE2T(i),
            pM, psG, nullptr, nullptr, nullptr, NN);
        {
            long n = (long)NE * (HD / 4);
            k_scatter<<<(int)((n + 255) / 256), 256>>>(esrc, etgt);
        }
        {
            int n = NN * (HD / 4);
            k_update<<<(n + 255) / 256, 256>>>();
        }
    }
    k_gemm_bf<3, HD, HD><<<dim3(HD / 64, blocksM), 256>>>(
        pxh, pxl, pWth + WPT, pWtl + WPT,
        py, nullptr, gidx, nullptr, nullptr, NN);
    k_mlp<<<NG, HD>>>(counts, Wfc1, bfc1, Wfc2, bfc2, Wr, br, out);
}

// round 9
// speedup vs baseline: 1.1829x; 1.0790x over previous
#include <cuda_runtime.h>
#include <cuda_bf16.h>
#include <cuda_fp16.h>
#include <cstdint>
#include <math.h>

#define NN 100000
#define NE 600000
#define NG 512
#define HD 128
#define EF 256
#define NCONV 3

// ---- scratch (device globals) ----
__device__ float g_x[NN * HD];
__device__ __nv_bfloat16 g_xh[NN * HD];
__device__ __nv_bfloat16 g_xl[NN * HD];
__device__ __half g_Af[NN * EF];          // sp(x@We1) as single fp16
__device__ float g_sG[NN * HD];
__device__ float g_M[NN * HD];
__device__ float g_agg[NN * HD];
__device__ float g_y[NG * HD];
// bf16 split weights: per conv [We1|Wg] concat [384][128], then WpT [128][128]
#define WCAT(c) ((c) * 49152)
#define WPT 147456
__device__ __nv_bfloat16 g_Wth[163840];
__device__ __nv_bfloat16 g_Wtl[163840];
// fp16 split We2T [c][n=128][k=256]
#define WE2F(c) ((c) * 32768)
__device__ __half g_W2h[98304];
__device__ __half g_W2l[98304];

// fast softplus / sigmoid (MUFU; abs err ~1e-6, tolerance 1e-3)
__device__ __forceinline__ float sp_(float x) {
    return fmaxf(x, 0.f) + __logf(1.f + __expf(-fabsf(x)));
}
__device__ __forceinline__ float sigm_(float x) {
    return 1.f / (1.f + __expf(-x));
}
__device__ __forceinline__ void split_bf(float x, __nv_bfloat16& h, __nv_bfloat16& l) {
    h = __float2bfloat16(x);
    l = __float2bfloat16(x - __bfloat162float(h));
}

__global__ void k_wsplit_all(const float* __restrict__ Wg, const float* __restrict__ We1,
                             const float* __restrict__ We2, const float* __restrict__ Wp) {
    int i = blockIdx.x * blockDim.x + threadIdx.x;
    if (i >= 262144) return;
    if (i < 147456) {                          // concat [c][n=384][k=128] -> bf16 split
        int c = i / 49152, j = i % 49152;
        int n = j / HD, k = j % HD;
        float w = (n < EF) ? We1[c * 32768 + k * EF + n]
                           : Wg[c * 16384 + k * HD + (n - EF)];
        __nv_bfloat16 h, l;
        split_bf(w, h, l);
        g_Wth[i] = h;
        g_Wtl[i] = l;
    } else if (i < 163840) {                   // WpT [n=128][k=128] -> bf16 split
        int j = i - 147456;
        int n = j / HD, k = j % HD;
        float w = Wp[k * HD + n];
        __nv_bfloat16 h, l;
        split_bf(w, h, l);
        g_Wth[i] = h;
        g_Wtl[i] = l;
    } else {                                   // We2T [c][n=128][k=256] -> fp16 split
        int j = i - 163840;
        int c = j / 32768, jj = j % 32768;
        int n = jj >> 8, k = jj & 255;
        float w = We2[c * 32768 + k * HD + n];
        __half h = __float2half_rn(w);
        __half l = __float2half_rn(w - __half2float(h));
        g_W2h[j] = h;
        g_W2l[j] = l;
    }
}

__global__ void k_zero_y() {
    int i = blockIdx.x * blockDim.x + threadIdx.x;
    if (i < NG * HD / 4) ((float4*)g_y)[i] = make_float4(0.f, 0.f, 0.f, 0.f);
}

__device__ __forceinline__ void store_split4(int i4, float4 v) {
    __nv_bfloat16 h0, h1, h2, h3, l0, l1, l2, l3;
    split_bf(v.x, h0, l0); split_bf(v.y, h1, l1);
    split_bf(v.z, h2, l2); split_bf(v.w, h3, l3);
    ((__nv_bfloat162*)g_xh)[i4 * 2] = __nv_bfloat162(h0, h1);
    ((__nv_bfloat162*)g_xh)[i4 * 2 + 1] = __nv_bfloat162(h2, h3);
    ((__nv_bfloat162*)g_xl)[i4 * 2] = __nv_bfloat162(l0, l1);
    ((__nv_bfloat162*)g_xl)[i4 * 2 + 1] = __nv_bfloat162(l2, l3);
}

__global__ void k_embed(const int* __restrict__ nodes, const float* __restrict__ embed) {
    int i = blockIdx.x * blockDim.x + threadIdx.x;
    if (i >= NN * (HD / 4)) return;
    int node = nodes[i >> 5];
    float4 v = ((const float4*)embed)[node * 32 + (i & 31)];
    ((float4*)g_x)[i] = v;
    store_split4(i, v);
}

// ---- shared PTX helpers ----
#define LDA 40

__device__ __forceinline__ void cp16(uint32_t dst, const void* src, bool pred) {
    int sz = pred ? 16 : 0;
    asm volatile("cp.async.cg.shared.global [%0], [%1], 16, %2;"
                 :: "r"(dst), "l"(src), "r"(sz));
}
__device__ __forceinline__ void cp_commit() {
    asm volatile("cp.async.commit_group;");
}
template <int N_>
__device__ __forceinline__ void cp_wait() {
    asm volatile("cp.async.wait_group %0;" :: "n"(N_));
}
__device__ __forceinline__ void ldm_x4(uint32_t addr, uint32_t r[4]) {
    asm volatile("ldmatrix.sync.aligned.m8n8.x4.shared.b16 {%0,%1,%2,%3},[%4];"
                 : "=r"(r[0]), "=r"(r[1]), "=r"(r[2]), "=r"(r[3]) : "r"(addr));
}
__device__ __forceinline__ void mma_bf(float c[4], const uint32_t a[4],
                                       uint32_t b0, uint32_t b1) {
    asm volatile(
        "mma.sync.aligned.m16n8k16.row.col.f32.bf16.bf16.f32 "
        "{%0,%1,%2,%3},{%4,%5,%6,%7},{%8,%9},{%0,%1,%2,%3};"
        : "+f"(c[0]), "+f"(c[1]), "+f"(c[2]), "+f"(c[3])
        : "r"(a[0]), "r"(a[1]), "r"(a[2]), "r"(a[3]), "r"(b0), "r"(b1));
}
__device__ __forceinline__ void mma_f16(float c[4], const uint32_t a[4],
                                        uint32_t b0, uint32_t b1) {
    asm volatile(
        "mma.sync.aligned.m16n8k16.row.col.f32.f16.f16.f32 "
        "{%0,%1,%2,%3},{%4,%5,%6,%7},{%8,%9},{%0,%1,%2,%3};"
        : "+f"(c[0]), "+f"(c[1]), "+f"(c[2]), "+f"(c[3])
        : "r"(a[0]), "r"(a[1]), "r"(a[2]), "r"(a[3]), "r"(b0), "r"(b1));
}

// ======================================================================
// bf16 split-3 GEMM (x-based). Block 128x64x32, 8 warps, 2-stage cp.async.
// EPI: 3 atomicAdd C[gidx] (pooling) ;
//      4 merged: n<256 -> fp16(softplus)->Af (stride 256),
//                n>=256 -> sigmoid->C (stride 128)
// ======================================================================
template <int EPI, int NT_, int KT_>
__global__ void __launch_bounds__(256) k_gemm_bf(
    const __nv_bfloat16* __restrict__ Ah, const __nv_bfloat16* __restrict__ Al,
    const __nv_bfloat16* __restrict__ Bh, const __nv_bfloat16* __restrict__ Bl,
    float* __restrict__ C, const int* __restrict__ gidx, __half* __restrict__ Af,
    int M) {
    constexpr int N = NT_;
    constexpr int K = KT_;
    constexpr int T = K / 32;

    __shared__ __nv_bfloat16 sA[2][2][128 * LDA];
    __shared__ __nv_bfloat16 sB[2][2][64 * LDA];

    const int tid = threadIdx.x;
    const int lane = tid & 31;
    const int warp = tid >> 5;
    const int wm = warp >> 1;
    const int wn = warp & 1;
    const int m0 = blockIdx.y * 128;
    const int n0 = blockIdx.x * 64;

    float acc[2][4][4];
#pragma unroll
    for (int i = 0; i < 2; i++)
#pragma unroll
        for (int j = 0; j < 4; j++)
#pragma unroll
            for (int q = 0; q < 4; q++) acc[i][j][q] = 0.f;

    uint32_t aB[2][2], bB[2][2];
#pragma unroll
    for (int st = 0; st < 2; st++)
#pragma unroll
        for (int hl = 0; hl < 2; hl++) {
            aB[st][hl] = (uint32_t)__cvta_generic_to_shared(&sA[st][hl][0]);
            bB[st][hl] = (uint32_t)__cvta_generic_to_shared(&sB[st][hl][0]);
        }

    const int a_r0 = tid >> 2;
    const int a_kc = (tid & 3) * 8;
    const int b_r = tid >> 2;
    const int b_kc = (tid & 3) * 8;

    const int a_row = ((lane >> 3) & 1) * 8 + (lane & 7);
    const int a_kof = (lane >> 4) * 8;
    const int b_row = ((lane >> 4) & 1) * 8 + (lane & 7);
    const int b_kof = ((lane >> 3) & 1) * 8;

    const bool pA0 = (m0 + a_r0) < M;
    const bool pA1 = (m0 + a_r0 + 64) < M;
    const uint32_t aOff0 = (uint32_t)(a_r0 * LDA + a_kc) * 2u;
    const uint32_t aOff1 = (uint32_t)((a_r0 + 64) * LDA + a_kc) * 2u;
    const uint32_t bOff = (uint32_t)(b_r * LDA + b_kc) * 2u;
    const __nv_bfloat16* gAh0 = Ah + (pA0 ? (long)(m0 + a_r0) * K + a_kc : 0);
    const __nv_bfloat16* gAl0 = Al + (pA0 ? (long)(m0 + a_r0) * K + a_kc : 0);
    const __nv_bfloat16* gAh1 = Ah + (pA1 ? (long)(m0 + a_r0 + 64) * K + a_kc : 0);
    const __nv_bfloat16* gAl1 = Al + (pA1 ? (long)(m0 + a_r0 + 64) * K + a_kc : 0);
    const __nv_bfloat16* gBh = Bh + (long)(n0 + b_r) * K + b_kc;
    const __nv_bfloat16* gBl = Bl + (long)(n0 + b_r) * K + b_kc;

#define LOAD_STAGE(st, k0)                                   \
    do {                                                     \
        cp16(aB[st][0] + aOff0, gAh0 + (k0), pA0);           \
        cp16(aB[st][1] + aOff0, gAl0 + (k0), pA0);           \
        cp16(aB[st][0] + aOff1, gAh1 + (k0), pA1);           \
        cp16(aB[st][1] + aOff1, gAl1 + (k0), pA1);           \
        cp16(bB[st][0] + bOff, gBh + (k0), true);            \
        cp16(bB[st][1] + bOff, gBl + (k0), true);            \
        cp_commit();                                         \
    } while (0)

    LOAD_STAGE(0, 0);

#pragma unroll
    for (int kt = 0; kt < T; kt++) {
        if (kt + 1 < T) {
            LOAD_STAGE((kt + 1) & 1, (kt + 1) * 32);
            cp_wait<1>();
        } else {
            cp_wait<0>();
        }
        __syncthreads();

        const int st = kt & 1;
#pragma unroll
        for (int ks = 0; ks < 32; ks += 16) {
            uint32_t fah[2][4], fal[2][4], fbh[2][4], fbl[2][4];
#pragma unroll
            for (int mt = 0; mt < 2; mt++) {
                uint32_t off = (uint32_t)((wm * 32 + mt * 16 + a_row) * LDA + ks + a_kof) * 2u;
                ldm_x4(aB[st][0] + off, fah[mt]);
                ldm_x4(aB[st][1] + off, fal[mt]);
            }
#pragma unroll
            for (int np = 0; np < 2; np++) {
                uint32_t off = (uint32_t)((wn * 32 + np * 16 + b_row) * LDA + ks + b_kof) * 2u;
                ldm_x4(bB[st][0] + off, fbh[np]);
                ldm_x4(bB[st][1] + off, fbl[np]);
            }
#pragma unroll
            for (int term = 0; term < 3; term++) {
#pragma unroll
                for (int mt = 0; mt < 2; mt++) {
#pragma unroll
                    for (int nt = 0; nt < 4; nt++) {
                        uint32_t b0, b1;
                        const uint32_t* fa;
                        if (term == 0) {
                            fa = fah[mt];
                            b0 = fbh[nt >> 1][(nt & 1) * 2];
                            b1 = fbh[nt >> 1][(nt & 1) * 2 + 1];
                        } else if (term == 1) {
                            fa = fah[mt];
                            b0 = fbl[nt >> 1][(nt & 1) * 2];
                            b1 = fbl[nt >> 1][(nt & 1) * 2 + 1];
                        } else {
                            fa = fal[mt];
                            b0 = fbh[nt >> 1][(nt & 1) * 2];
                            b1 = fbh[nt >> 1][(nt & 1) * 2 + 1];
                        }
                        mma_bf(acc[mt][nt], fa, b0, b1);
                    }
                }
            }
        }
        __syncthreads();
    }
#undef LOAD_STAGE

#pragma unroll
    for (int mt = 0; mt < 2; mt++) {
#pragma unroll
        for (int nt = 0; nt < 4; nt++) {
            int rbase = m0 + wm * 32 + mt * 16 + (lane >> 2);
            int col = n0 + wn * 32 + nt * 8 + (lane & 3) * 2;
            float* c = acc[mt][nt];
#pragma unroll
            for (int half = 0; half < 2; half++) {
                int row = rbase + half * 8;
                if (row >= M) continue;
                float v0 = c[half * 2], v1 = c[half * 2 + 1];
                if (EPI == 4 && n0 < 256) {
                    long base = (long)row * 256 + col;
                    *reinterpret_cast<__half2*>(&Af[base]) =
                        __floats2half2_rn(sp_(v0), sp_(v1));
                } else if (EPI == 4) {
                    long base = (long)row * HD + (col - 256);
                    *reinterpret_cast<float2*>(&C[base]) = make_float2(sigm_(v0), sigm_(v1));
                } else {  // EPI == 3
                    int seg = gidx[row];
                    atomicAdd(reinterpret_cast<float2*>(&C[(long)seg * N + col]),
                              make_float2(v0, v1));
                }
            }
        }
    }
}

// ======================================================================
// fp16 message GEMM: M = sG * sp( A[M,256] @ We2^T ), A single fp16,
// B split-2 fp16 [128][256]. 2 MMA terms. Block 128x64x32, 8 warps.
// ======================================================================
__global__ void __launch_bounds__(256) k_gemm_f16(
    const __half* __restrict__ A, const __half* __restrict__ Bh,
    const __half* __restrict__ Bl, float* __restrict__ C,
    const float* __restrict__ Gb, int M) {
    constexpr int K = EF;
    constexpr int T = K / 32;

    __shared__ __half sA[2][128 * LDA];
    __shared__ __half sB[2][2][64 * LDA];

    const int tid = threadIdx.x;
    const int lane = tid & 31;
    const int warp = tid >> 5;
    const int wm = warp >> 1;
    const int wn = warp & 1;
    const int m0 = blockIdx.y * 128;
    const int n0 = blockIdx.x * 64;

    float acc[2][4][4];
#pragma unroll
    for (int i = 0; i < 2; i++)
#pragma unroll
        for (int j = 0; j < 4; j++)
#pragma unroll
            for (int q = 0; q < 4; q++) acc[i][j][q] = 0.f;

    uint32_t aB[2], bB[2][2];
#pragma unroll
    for (int st = 0; st < 2; st++) {
        aB[st] = (uint32_t)__cvta_generic_to_shared(&sA[st][0]);
#pragma unroll
        for (int hl = 0; hl < 2; hl++)
            bB[st][hl] = (uint32_t)__cvta_generic_to_shared(&sB[st][hl][0]);
    }

    const int a_r0 = tid >> 2;
    const int a_kc = (tid & 3) * 8;
    const int b_r = tid >> 2;
    const int b_kc = (tid & 3) * 8;

    const int a_row = ((lane >> 3) & 1) * 8 + (lane & 7);
    const int a_kof = (lane >> 4) * 8;
    const int b_row = ((lane >> 4) & 1) * 8 + (lane & 7);
    const int b_kof = ((lane >> 3) & 1) * 8;

    const bool pA0 = (m0 + a_r0) < M;
    const bool pA1 = (m0 + a_r0 + 64) < M;
    const uint32_t aOff0 = (uint32_t)(a_r0 * LDA + a_kc) * 2u;
    const uint32_t aOff1 = (uint32_t)((a_r0 + 64) * LDA + a_kc) * 2u;
    const uint32_t bOff = (uint32_t)(b_r * LDA + b_kc) * 2u;
    const __half* gA0 = A + (pA0 ? (long)(m0 + a_r0) * K + a_kc : 0);
    const __half* gA1 = A + (pA1 ? (long)(m0 + a_r0 + 64) * K + a_kc : 0);
    const __half* gBh = Bh + (long)(n0 + b_r) * K + b_kc;
    const __half* gBl = Bl + (long)(n0 + b_r) * K + b_kc;

#define LOAD_STAGE_F(st, k0)                         \
    do {                                             \
        cp16(aB[st] + aOff0, gA0 + (k0), pA0);       \
        cp16(aB[st] + aOff1, gA1 + (k0), pA1);       \
        cp16(bB[st][0] + bOff, gBh + (k0), true);    \
        cp16(bB[st][1] + bOff, gBl + (k0), true);    \
        cp_commit();                                 \
    } while (0)

    LOAD_STAGE_F(0, 0);

#pragma unroll
    for (int kt = 0; kt < T; kt++) {
        if (kt + 1 < T) {
            LOAD_STAGE_F((kt + 1) & 1, (kt + 1) * 32);
            cp_wait<1>();
        } else {
            cp_wait<0>();
        }
        __syncthreads();

        const int st = kt & 1;
#pragma unroll
        for (int ks = 0; ks < 32; ks += 16) {
            uint32_t fa[2][4], fbh[2][4], fbl[2][4];
#pragma unroll
            for (int mt = 0; mt < 2; mt++) {
                uint32_t off = (uint32_t)((wm * 32 + mt * 16 + a_row) * LDA + ks + a_kof) * 2u;
                ldm_x4(aB[st] + off, fa[mt]);
            }
#pragma unroll
            for (int np = 0; np < 2; np++) {
                uint32_t off = (uint32_t)((wn * 32 + np * 16 + b_row) * LDA + ks + b_kof) * 2u;
                ldm_x4(bB[st][0] + off, fbh[np]);
                ldm_x4(bB[st][1] + off, fbl[np]);
            }
#pragma unroll
            for (int term = 0; term < 2; term++) {
#pragma unroll
                for (int mt = 0; mt < 2; mt++) {
#pragma unroll
                    for (int nt = 0; nt < 4; nt++) {
                        uint32_t b0, b1;
                        if (term == 0) {
                            b0 = fbh[nt >> 1][(nt & 1) * 2];
                            b1 = fbh[nt >> 1][(nt & 1) * 2 + 1];
                        } else {
                            b0 = fbl[nt >> 1][(nt & 1) * 2];
                            b1 = fbl[nt >> 1][(nt & 1) * 2 + 1];
                        }
                        mma_f16(acc[mt][nt], fa[mt], b0, b1);
                    }
                }
            }
        }
        __syncthreads();
    }
#undef LOAD_STAGE_F

#pragma unroll
    for (int mt = 0; mt < 2; mt++) {
#pragma unroll
        for (int nt = 0; nt < 4; nt++) {
            int rbase = m0 + wm * 32 + mt * 16 + (lane >> 2);
            int col = n0 + wn * 32 + nt * 8 + (lane & 3) * 2;
            float* c = acc[mt][nt];
#pragma unroll
            for (int half = 0; half < 2; half++) {
                int row = rbase + half * 8;
                if (row >= M) continue;
                long base = (long)row * HD + col;
                float2 g2 = *reinterpret_cast<const float2*>(&Gb[base]);
                *reinterpret_cast<float2*>(&C[base]) =
                    make_float2(g2.x * sp_(c[half * 2]), g2.y * sp_(c[half * 2 + 1]));
            }
        }
    }
}

// ---- edge scatter with float4 vector atomics ----
__global__ void k_scatter(const int* __restrict__ src, const int* __restrict__ tgt) {
    long i = (long)blockIdx.x * blockDim.x + threadIdx.x;
    if (i >= (long)NE * (HD / 4)) return;
    int e = (int)(i >> 5);
    int c = (int)(i & 31);
    int s = src[e], t = tgt[e];
    float4 v = ((const float4*)g_M)[(long)s * 32 + c];
    atomicAdd(reinterpret_cast<float4*>(&g_agg[(long)t * HD + c * 4]), v);
}

__global__ void k_update() {
    int i = blockIdx.x * blockDim.x + threadIdx.x;
    if (i >= NN * (HD / 4)) return;
    float4 a = ((float4*)g_agg)[i];
    float4 x = ((float4*)g_x)[i];
    x.x += sp_(a.x);
    x.y += sp_(a.y);
    x.z += sp_(a.z);
    x.w += sp_(a.w);
    ((float4*)g_x)[i] = x;
    store_split4(i, x);
    ((float4*)g_agg)[i] = make_float4(0.f, 0.f, 0.f, 0.f);
}

__global__ void k_mlp(const float* __restrict__ counts,
                      const float* __restrict__ Wfc1, const float* __restrict__ bfc1,
                      const float* __restrict__ Wfc2, const float* __restrict__ bfc2,
                      const float* __restrict__ Wr, const float* __restrict__ br,
                      float* __restrict__ out) {
    __shared__ float s0[HD];
    __shared__ float s1[HD];
    __shared__ float red[HD];
    int g = blockIdx.x, t = threadIdx.x;

    float yv = g_y[g * HD + t] / counts[g];
    s0[t] = sp_(yv);
    __syncthreads();

    float acc = bfc1[t];
#pragma unroll 8
    for (int k = 0; k < HD; k++) acc += s0[k] * Wfc1[k * HD + t];
    s1[t] = sp_(acc);
    __syncthreads();

    acc = bfc2[t];
#pragma unroll 8
    for (int k = 0; k < HD; k++) acc += s1[k] * Wfc2[k * HD + t];
    float h2 = sp_(acc);

    red[t] = h2 * Wr[t];
    __syncthreads();
    for (int s = HD / 2; s > 0; s >>= 1) {
        if (t < s) red[t] += red[t + s];
        __syncthreads();
    }
    if (t == 0) out[g] = red[0] + br[0];
}

extern "C" void kernel_launch(void* const* d_in, const int* in_sizes, int n_in,
                              void* d_out, int out_size) {
    const int* nodes = (const int*)d_in[0];
    const int* esrc = (const int*)d_in[1];
    const int* etgt = (const int*)d_in[2];
    const int* gidx = (const int*)d_in[3];
    const float* counts = (const float*)d_in[4];
    const float* embed = (const float*)d_in[5];
    const float* Wg = (const float*)d_in[6];
    const float* We1 = (const float*)d_in[7];
    const float* We2 = (const float*)d_in[8];
    const float* Wp = (const float*)d_in[9];
    const float* Wfc1 = (const float*)d_in[10];
    const float* bfc1 = (const float*)d_in[11];
    const float* Wfc2 = (const float*)d_in[12];
    const float* bfc2 = (const float*)d_in[13];
    const float* Wr = (const float*)d_in[14];
    const float* br = (const float*)d_in[15];
    float* out = (float*)d_out;

    __nv_bfloat16 *pxh, *pxl, *pWth, *pWtl;
    __half *pAf, *pW2h, *pW2l;
    float *psG, *pM, *py;
    cudaGetSymbolAddress((void**)&pxh, g_xh);
    cudaGetSymbolAddress((void**)&pxl, g_xl);
    cudaGetSymbolAddress((void**)&pAf, g_Af);
    cudaGetSymbolAddress((void**)&pWth, g_Wth);
    cudaGetSymbolAddress((void**)&pWtl, g_Wtl);
    cudaGetSymbolAddress((void**)&pW2h, g_W2h);
    cudaGetSymbolAddress((void**)&pW2l, g_W2l);
    cudaGetSymbolAddress((void**)&psG, g_sG);
    cudaGetSymbolAddress((void**)&pM, g_M);
    cudaGetSymbolAddress((void**)&py, g_y);

    const int blocksM = (NN + 127) / 128;

    k_wsplit_all<<<(262144 + 255) / 256, 256>>>(Wg, We1, We2, Wp);
    k_zero_y<<<(NG * HD / 4 + 255) / 256, 256>>>();
    {
        int n = NN * (HD / 4);
        k_embed<<<(n + 255) / 256, 256>>>(nodes, embed);
    }
    for (int i = 0; i < NCONV; i++) {
        // merged: sp(x@We1) -> Af fp16 (n-tiles 0..3) AND sigmoid(x@Wg) -> sG (4,5)
        k_gemm_bf<4, 384, HD><<<dim3(384 / 64, blocksM), 256>>>(
            pxh, pxl, pWth + WCAT(i), pWtl + WCAT(i),
            psG, nullptr, pAf, NN);
        // M = sG * sp(A @ We2), fp16 path
        k_gemm_f16<<<dim3(HD / 64, blocksM), 256>>>(
            pAf, pW2h + WE2F(i), pW2l + WE2F(i), pM, psG, NN);
        {
            long n = (long)NE * (HD / 4);
            k_scatter<<<(int)((n + 255) / 256), 256>>>(esrc, etgt);
        }
        {
            int n = NN * (HD / 4);
            k_update<<<(n + 255) / 256, 256>>>();
        }
    }
    k_gemm_bf<3, HD, HD><<<dim3(HD / 64, blocksM), 256>>>(
        pxh, pxl, pWth + WPT, pWtl + WPT,
        py, gidx, nullptr, NN);
    k_mlp<<<NG, HD>>>(counts, Wfc1, bfc1, Wfc2, bfc2, Wr, br, out);
}

// round 10
// speedup vs baseline: 1.3315x; 1.1257x over previous
#include <cuda_runtime.h>
#include <cuda_bf16.h>
#include <cuda_fp16.h>
#include <cstdint>
#include <math.h>

#define NN 100000
#define NE 600000
#define NG 512
#define HD 128
#define EF 256
#define NCONV 3

// ---- scratch (device globals) ----
__device__ float g_x[NN * HD];        // fp32 master node features
__device__ __half g_xf[NN * HD];      // fp16 MMA copy
__device__ __half g_Af[NN * EF];      // sp(x@We1) fp16
__device__ float g_sG[NN * HD];
__device__ float g_M[NN * HD];
__device__ float g_agg[NN * HD];
__device__ float g_y[NG * HD];
// fp16 split-2 weights: [We1|Wg] concat per conv, WpT, We2T per conv
#define WCAT(c) ((c) * 49152)
#define WPT 147456
#define WE2(c) (163840 + (c) * 32768)
__device__ __half g_Wfh[262144];
__device__ __half g_Wfl[262144];

// fast softplus / sigmoid (MUFU)
__device__ __forceinline__ float sp_(float x) {
    return fmaxf(x, 0.f) + __logf(1.f + __expf(-fabsf(x)));
}
__device__ __forceinline__ float sigm_(float x) {
    return 1.f / (1.f + __expf(-x));
}

__global__ void k_wsplit_all(const float* __restrict__ Wg, const float* __restrict__ We1,
                             const float* __restrict__ We2, const float* __restrict__ Wp) {
    int i = blockIdx.x * blockDim.x + threadIdx.x;
    if (i >= 262144) return;
    float w;
    if (i < 147456) {                          // concat [c][n=384][k=128]
        int c = i / 49152, j = i % 49152;
        int n = j / HD, k = j % HD;
        w = (n < EF) ? We1[c * 32768 + k * EF + n]
                     : Wg[c * 16384 + k * HD + (n - EF)];
    } else if (i < 163840) {                   // WpT [n=128][k=128]
        int j = i - 147456;
        int n = j / HD, k = j % HD;
        w = Wp[k * HD + n];
    } else {                                   // We2T [c][n=128][k=256]
        int j = i - 163840;
        int c = j / 32768, jj = j % 32768;
        int n = jj >> 8, k = jj & 255;
        w = We2[c * 32768 + k * HD + n];
    }
    __half h = __float2half_rn(w);
    __half l = __float2half_rn(w - __half2float(h));
    g_Wfh[i] = h;
    g_Wfl[i] = l;
}

__global__ void k_zero_y() {
    int i = blockIdx.x * blockDim.x + threadIdx.x;
    if (i < NG * HD / 4) ((float4*)g_y)[i] = make_float4(0.f, 0.f, 0.f, 0.f);
}

__global__ void k_embed(const int* __restrict__ nodes, const float* __restrict__ embed) {
    int i = blockIdx.x * blockDim.x + threadIdx.x;
    if (i >= NN * (HD / 4)) return;
    int node = nodes[i >> 5];
    float4 v = ((const float4*)embed)[node * 32 + (i & 31)];
    ((float4*)g_x)[i] = v;
    __half2 h0 = __floats2half2_rn(v.x, v.y);
    __half2 h1 = __floats2half2_rn(v.z, v.w);
    ((__half2*)g_xf)[i * 2] = h0;
    ((__half2*)g_xf)[i * 2 + 1] = h1;
}

// ---- PTX helpers ----
#define LDA 40

__device__ __forceinline__ void cp16(uint32_t dst, const void* src, bool pred) {
    int sz = pred ? 16 : 0;
    asm volatile("cp.async.cg.shared.global [%0], [%1], 16, %2;"
                 :: "r"(dst), "l"(src), "r"(sz));
}
__device__ __forceinline__ void cp_commit() {
    asm volatile("cp.async.commit_group;");
}
template <int N_>
__device__ __forceinline__ void cp_wait() {
    asm volatile("cp.async.wait_group %0;" :: "n"(N_));
}
__device__ __forceinline__ void ldm_x4(uint32_t addr, uint32_t r[4]) {
    asm volatile("ldmatrix.sync.aligned.m8n8.x4.shared.b16 {%0,%1,%2,%3},[%4];"
                 : "=r"(r[0]), "=r"(r[1]), "=r"(r[2]), "=r"(r[3]) : "r"(addr));
}
__device__ __forceinline__ void mma_f16(float c[4], const uint32_t a[4],
                                        uint32_t b0, uint32_t b1) {
    asm volatile(
        "mma.sync.aligned.m16n8k16.row.col.f32.f16.f16.f32 "
        "{%0,%1,%2,%3},{%4,%5,%6,%7},{%8,%9},{%0,%1,%2,%3};"
        : "+f"(c[0]), "+f"(c[1]), "+f"(c[2]), "+f"(c[3])
        : "r"(a[0]), "r"(a[1]), "r"(a[2]), "r"(a[3]), "r"(b0), "r"(b1));
}

// ======================================================================
// Unified fp16 2-term GEMM: C = epi( A[M,K] @ B^T ), A single fp16,
// B split-2 fp16 [N][K]. Block 128x64x32, 8 warps, 2-stage cp.async.
// EPI: 2 -> C = Gb * softplus(acc)      (message, stride 128)
//      3 -> atomicAdd C[gidx[row]]      (pooling, stride 128)
//      4 -> merged: n<256: Af = fp16(softplus(acc)) stride 256
//                   n>=256: C = sigmoid(acc) stride 128
// ======================================================================
template <int EPI, int NT_, int KT_>
__global__ void __launch_bounds__(256) k_g16(
    const __half* __restrict__ A, const __half* __restrict__ Bh,
    const __half* __restrict__ Bl, float* __restrict__ C,
    const float* __restrict__ Gb, const int* __restrict__ gidx,
    __half* __restrict__ Af, int M) {
    constexpr int K = KT_;
    constexpr int T = K / 32;

    __shared__ __half sA[2][128 * LDA];
    __shared__ __half sB[2][2][64 * LDA];

    const int tid = threadIdx.x;
    const int lane = tid & 31;
    const int warp = tid >> 5;
    const int wm = warp >> 1;
    const int wn = warp & 1;
    const int m0 = blockIdx.y * 128;
    const int n0 = blockIdx.x * 64;

    float acc[2][4][4];
#pragma unroll
    for (int i = 0; i < 2; i++)
#pragma unroll
        for (int j = 0; j < 4; j++)
#pragma unroll
            for (int q = 0; q < 4; q++) acc[i][j][q] = 0.f;

    uint32_t aB[2], bB[2][2];
#pragma unroll
    for (int st = 0; st < 2; st++) {
        aB[st] = (uint32_t)__cvta_generic_to_shared(&sA[st][0]);
#pragma unroll
        for (int hl = 0; hl < 2; hl++)
            bB[st][hl] = (uint32_t)__cvta_generic_to_shared(&sB[st][hl][0]);
    }

    const int a_r0 = tid >> 2;
    const int a_kc = (tid & 3) * 8;
    const int b_r = tid >> 2;
    const int b_kc = (tid & 3) * 8;

    const int a_row = ((lane >> 3) & 1) * 8 + (lane & 7);
    const int a_kof = (lane >> 4) * 8;
    const int b_row = ((lane >> 4) & 1) * 8 + (lane & 7);
    const int b_kof = ((lane >> 3) & 1) * 8;

    const bool pA0 = (m0 + a_r0) < M;
    const bool pA1 = (m0 + a_r0 + 64) < M;
    const uint32_t aOff0 = (uint32_t)(a_r0 * LDA + a_kc) * 2u;
    const uint32_t aOff1 = (uint32_t)((a_r0 + 64) * LDA + a_kc) * 2u;
    const uint32_t bOff = (uint32_t)(b_r * LDA + b_kc) * 2u;
    const __half* gA0 = A + (pA0 ? (long)(m0 + a_r0) * K + a_kc : 0);
    const __half* gA1 = A + (pA1 ? (long)(m0 + a_r0 + 64) * K + a_kc : 0);
    const __half* gBh = Bh + (long)(n0 + b_r) * K + b_kc;
    const __half* gBl = Bl + (long)(n0 + b_r) * K + b_kc;

#define LOAD_STAGE(st, k0)                           \
    do {                                             \
        cp16(aB[st] + aOff0, gA0 + (k0), pA0);       \
        cp16(aB[st] + aOff1, gA1 + (k0), pA1);       \
        cp16(bB[st][0] + bOff, gBh + (k0), true);    \
        cp16(bB[st][1] + bOff, gBl + (k0), true);    \
        cp_commit();                                 \
    } while (0)

    LOAD_STAGE(0, 0);

#pragma unroll
    for (int kt = 0; kt < T; kt++) {
        if (kt + 1 < T) {
            LOAD_STAGE((kt + 1) & 1, (kt + 1) * 32);
            cp_wait<1>();
        } else {
            cp_wait<0>();
        }
        __syncthreads();

        const int st = kt & 1;
#pragma unroll
        for (int ks = 0; ks < 32; ks += 16) {
            uint32_t fa[2][4], fbh[2][4], fbl[2][4];
#pragma unroll
            for (int mt = 0; mt < 2; mt++) {
                uint32_t off = (uint32_t)((wm * 32 + mt * 16 + a_row) * LDA + ks + a_kof) * 2u;
                ldm_x4(aB[st] + off, fa[mt]);
            }
#pragma unroll
            for (int np = 0; np < 2; np++) {
                uint32_t off = (uint32_t)((wn * 32 + np * 16 + b_row) * LDA + ks + b_kof) * 2u;
                ldm_x4(bB[st][0] + off, fbh[np]);
                ldm_x4(bB[st][1] + off, fbl[np]);
            }
#pragma unroll
            for (int term = 0; term < 2; term++) {
#pragma unroll
                for (int mt = 0; mt < 2; mt++) {
#pragma unroll
                    for (int nt = 0; nt < 4; nt++) {
                        uint32_t b0, b1;
                        if (term == 0) {
                            b0 = fbh[nt >> 1][(nt & 1) * 2];
                            b1 = fbh[nt >> 1][(nt & 1) * 2 + 1];
                        } else {
                            b0 = fbl[nt >> 1][(nt & 1) * 2];
                            b1 = fbl[nt >> 1][(nt & 1) * 2 + 1];
                        }
                        mma_f16(acc[mt][nt], fa[mt], b0, b1);
                    }
                }
            }
        }
        __syncthreads();
    }
#undef LOAD_STAGE

    // epilogue
#pragma unroll
    for (int mt = 0; mt < 2; mt++) {
#pragma unroll
        for (int nt = 0; nt < 4; nt++) {
            int rbase = m0 + wm * 32 + mt * 16 + (lane >> 2);
            int col = n0 + wn * 32 + nt * 8 + (lane & 3) * 2;
            float* c = acc[mt][nt];
#pragma unroll
            for (int half = 0; half < 2; half++) {
                int row = rbase + half * 8;
                if (row >= M) continue;
                float v0 = c[half * 2], v1 = c[half * 2 + 1];
                if (EPI == 4 && n0 < 256) {
                    long base = (long)row * 256 + col;
                    *reinterpret_cast<__half2*>(&Af[base]) =
                        __floats2half2_rn(sp_(v0), sp_(v1));
                } else if (EPI == 4) {
                    long base = (long)row * HD + (col - 256);
                    *reinterpret_cast<float2*>(&C[base]) = make_float2(sigm_(v0), sigm_(v1));
                } else if (EPI == 2) {
                    long base = (long)row * HD + col;
                    float2 g2 = *reinterpret_cast<const float2*>(&Gb[base]);
                    *reinterpret_cast<float2*>(&C[base]) =
                        make_float2(g2.x * sp_(v0), g2.y * sp_(v1));
                } else {  // EPI == 3
                    int seg = gidx[row];
                    atomicAdd(reinterpret_cast<float2*>(&C[(long)seg * HD + col]),
                              make_float2(v0, v1));
                }
            }
        }
    }
}

// ---- edge scatter with float4 vector atomics ----
__global__ void k_scatter(const int* __restrict__ src, const int* __restrict__ tgt) {
    long i = (long)blockIdx.x * blockDim.x + threadIdx.x;
    if (i >= (long)NE * (HD / 4)) return;
    int e = (int)(i >> 5);
    int c = (int)(i & 31);
    int s = src[e], t = tgt[e];
    float4 v = ((const float4*)g_M)[(long)s * 32 + c];
    atomicAdd(reinterpret_cast<float4*>(&g_agg[(long)t * HD + c * 4]), v);
}

// ---- node update: x += sp(agg); refresh fp16 copy; zero agg ----
__global__ void k_update() {
    int i = blockIdx.x * blockDim.x + threadIdx.x;
    if (i >= NN * (HD / 4)) return;
    float4 a = ((float4*)g_agg)[i];
    float4 x = ((float4*)g_x)[i];
    x.x += sp_(a.x);
    x.y += sp_(a.y);
    x.z += sp_(a.z);
    x.w += sp_(a.w);
    ((float4*)g_x)[i] = x;
    ((__half2*)g_xf)[i * 2] = __floats2half2_rn(x.x, x.y);
    ((__half2*)g_xf)[i * 2 + 1] = __floats2half2_rn(x.z, x.w);
    ((float4*)g_agg)[i] = make_float4(0.f, 0.f, 0.f, 0.f);
}

__global__ void k_mlp(const float* __restrict__ counts,
                      const float* __restrict__ Wfc1, const float* __restrict__ bfc1,
                      const float* __restrict__ Wfc2, const float* __restrict__ bfc2,
                      const float* __restrict__ Wr, const float* __restrict__ br,
                      float* __restrict__ out) {
    __shared__ float s0[HD];
    __shared__ float s1[HD];
    __shared__ float red[HD];
    int g = blockIdx.x, t = threadIdx.x;

    float yv = g_y[g * HD + t] / counts[g];
    s0[t] = sp_(yv);
    __syncthreads();

    float acc = bfc1[t];
#pragma unroll 8
    for (int k = 0; k < HD; k++) acc += s0[k] * Wfc1[k * HD + t];
    s1[t] = sp_(acc);
    __syncthreads();

    acc = bfc2[t];
#pragma unroll 8
    for (int k = 0; k < HD; k++) acc += s1[k] * Wfc2[k * HD + t];
    float h2 = sp_(acc);

    red[t] = h2 * Wr[t];
    __syncthreads();
    for (int s = HD / 2; s > 0; s >>= 1) {
        if (t < s) red[t] += red[t + s];
        __syncthreads();
    }
    if (t == 0) out[g] = red[0] + br[0];
}

extern "C" void kernel_launch(void* const* d_in, const int* in_sizes, int n_in,
                              void* d_out, int out_size) {
    const int* nodes = (const int*)d_in[0];
    const int* esrc = (const int*)d_in[1];
    const int* etgt = (const int*)d_in[2];
    const int* gidx = (const int*)d_in[3];
    const float* counts = (const float*)d_in[4];
    const float* embed = (const float*)d_in[5];
    const float* Wg = (const float*)d_in[6];
    const float* We1 = (const float*)d_in[7];
    const float* We2 = (const float*)d_in[8];
    const float* Wp = (const float*)d_in[9];
    const float* Wfc1 = (const float*)d_in[10];
    const float* bfc1 = (const float*)d_in[11];
    const float* Wfc2 = (const float*)d_in[12];
    const float* bfc2 = (const float*)d_in[13];
    const float* Wr = (const float*)d_in[14];
    const float* br = (const float*)d_in[15];
    float* out = (float*)d_out;

    __half *pxf, *pAf, *pWfh, *pWfl;
    float *psG, *pM, *py;
    cudaGetSymbolAddress((void**)&pxf, g_xf);
    cudaGetSymbolAddress((void**)&pAf, g_Af);
    cudaGetSymbolAddress((void**)&pWfh, g_Wfh);
    cudaGetSymbolAddress((void**)&pWfl, g_Wfl);
    cudaGetSymbolAddress((void**)&psG, g_sG);
    cudaGetSymbolAddress((void**)&pM, g_M);
    cudaGetSymbolAddress((void**)&py, g_y);

    const int blocksM = (NN + 127) / 128;

    k_wsplit_all<<<(262144 + 255) / 256, 256>>>(Wg, We1, We2, Wp);
    k_zero_y<<<(NG * HD / 4 + 255) / 256, 256>>>();
    {
        int n = NN * (HD / 4);
        k_embed<<<(n + 255) / 256, 256>>>(nodes, embed);
    }
    for (int i = 0; i < NCONV; i++) {
        // merged: sp(x@We1) -> Af (n-tiles 0..3) AND sigmoid(x@Wg) -> sG (4,5)
        k_g16<4, 384, HD><<<dim3(384 / 64, blocksM), 256>>>(
            pxf, pWfh + WCAT(i), pWfl + WCAT(i),
            psG, nullptr, nullptr, pAf, NN);
        // M = sG * sp(A @ We2)
        k_g16<2, HD, EF><<<dim3(HD / 64, blocksM), 256>>>(
            pAf, pWfh + WE2(i), pWfl + WE2(i),
            pM, psG, nullptr, nullptr, NN);
        {
            long n = (long)NE * (HD / 4);
            k_scatter<<<(int)((n + 255) / 256), 256>>>(esrc, etgt);
        }
        {
            int n = NN * (HD / 4);
            k_update<<<(n + 255) / 256, 256>>>();
        }
    }
    // pooling with fused segment atomics
    k_g16<3, HD, HD><<<dim3(HD / 64, blocksM), 256>>>(
        pxf, pWfh + WPT, pWfl + WPT,
        py, nullptr, gidx, nullptr, NN);
    k_mlp<<<NG, HD>>>(counts, Wfc1, bfc1, Wfc2, bfc2, Wr, br, out);
}

// round 11
// speedup vs baseline: 1.3851x; 1.0402x over previous
#include <cuda_runtime.h>
#include <cuda_bf16.h>
#include <cuda_fp16.h>
#include <cstdint>
#include <math.h>

#define NN 100000
#define NE 600000
#define NG 512
#define HD 128
#define EF 256
#define NCONV 3

// ---- scratch (device globals) ----
__device__ float g_x[NN * HD];        // fp32 master node features
__device__ __half g_xf[NN * HD];      // fp16 MMA copy
__device__ __half g_Af[NN * EF];      // sp(x@We1) fp16
__device__ __half g_sG[NN * HD];      // sigmoid gate fp16
__device__ __half g_M[NN * HD];       // message fp16
__device__ float g_agg[NN * HD];      // fp32 accumulator
__device__ float g_y[NG * HD];
// fp16 split-2 weights: [We1|Wg] concat per conv, WpT, We2T per conv
#define WCAT(c) ((c) * 49152)
#define WPT 147456
#define WE2(c) (163840 + (c) * 32768)
__device__ __half g_Wfh[262144];
__device__ __half g_Wfl[262144];

// fast softplus / sigmoid (MUFU)
__device__ __forceinline__ float sp_(float x) {
    return fmaxf(x, 0.f) + __logf(1.f + __expf(-fabsf(x)));
}
__device__ __forceinline__ float sigm_(float x) {
    return 1.f / (1.f + __expf(-x));
}

__global__ void k_wsplit_all(const float* __restrict__ Wg, const float* __restrict__ We1,
                             const float* __restrict__ We2, const float* __restrict__ Wp) {
    int i = blockIdx.x * blockDim.x + threadIdx.x;
    if (i >= 262144) return;
    float w;
    if (i < 147456) {                          // concat [c][n=384][k=128]
        int c = i / 49152, j = i % 49152;
        int n = j / HD, k = j % HD;
        w = (n < EF) ? We1[c * 32768 + k * EF + n]
                     : Wg[c * 16384 + k * HD + (n - EF)];
    } else if (i < 163840) {                   // WpT [n=128][k=128]
        int j = i - 147456;
        int n = j / HD, k = j % HD;
        w = Wp[k * HD + n];
    } else {                                   // We2T [c][n=128][k=256]
        int j = i - 163840;
        int c = j / 32768, jj = j % 32768;
        int n = jj >> 8, k = jj & 255;
        w = We2[c * 32768 + k * HD + n];
    }
    __half h = __float2half_rn(w);
    __half l = __float2half_rn(w - __half2float(h));
    g_Wfh[i] = h;
    g_Wfl[i] = l;
}

__global__ void k_zero_y() {
    int i = blockIdx.x * blockDim.x + threadIdx.x;
    if (i < NG * HD / 4) ((float4*)g_y)[i] = make_float4(0.f, 0.f, 0.f, 0.f);
}

__global__ void k_embed(const int* __restrict__ nodes, const float* __restrict__ embed) {
    int i = blockIdx.x * blockDim.x + threadIdx.x;
    if (i >= NN * (HD / 4)) return;
    int node = nodes[i >> 5];
    float4 v = ((const float4*)embed)[node * 32 + (i & 31)];
    ((float4*)g_x)[i] = v;
    ((__half2*)g_xf)[i * 2] = __floats2half2_rn(v.x, v.y);
    ((__half2*)g_xf)[i * 2 + 1] = __floats2half2_rn(v.z, v.w);
}

// ---- PTX helpers ----
#define LDA 40

__device__ __forceinline__ void cp16(uint32_t dst, const void* src, bool pred) {
    int sz = pred ? 16 : 0;
    asm volatile("cp.async.cg.shared.global [%0], [%1], 16, %2;"
                 :: "r"(dst), "l"(src), "r"(sz));
}
__device__ __forceinline__ void cp_commit() {
    asm volatile("cp.async.commit_group;");
}
template <int N_>
__device__ __forceinline__ void cp_wait() {
    asm volatile("cp.async.wait_group %0;" :: "n"(N_));
}
__device__ __forceinline__ void ldm_x4(uint32_t addr, uint32_t r[4]) {
    asm volatile("ldmatrix.sync.aligned.m8n8.x4.shared.b16 {%0,%1,%2,%3},[%4];"
                 : "=r"(r[0]), "=r"(r[1]), "=r"(r[2]), "=r"(r[3]) : "r"(addr));
}
__device__ __forceinline__ void mma_f16(float c[4], const uint32_t a[4],
                                        uint32_t b0, uint32_t b1) {
    asm volatile(
        "mma.sync.aligned.m16n8k16.row.col.f32.f16.f16.f32 "
        "{%0,%1,%2,%3},{%4,%5,%6,%7},{%8,%9},{%0,%1,%2,%3};"
        : "+f"(c[0]), "+f"(c[1]), "+f"(c[2]), "+f"(c[3])
        : "r"(a[0]), "r"(a[1]), "r"(a[2]), "r"(a[3]), "r"(b0), "r"(b1));
}

// ======================================================================
// Unified fp16 2-term GEMM: C = epi( A[M,K] @ B^T ), A single fp16,
// B split-2 fp16 [N][K]. Block 128x64x32, 8 warps, 2-stage cp.async.
// EPI: 2 -> Out16 = Gb16 * softplus(acc)  (message fp16, stride 128)
//      3 -> atomicAdd Cf[gidx[row]]       (pooling fp32, stride 128)
//      4 -> merged: n<256: Out16 = fp16(softplus(acc)) stride 256
//                   n>=256: Out2 = fp16(sigmoid(acc))  stride 128
// ======================================================================
template <int EPI, int NT_, int KT_>
__global__ void __launch_bounds__(256) k_g16(
    const __half* __restrict__ A, const __half* __restrict__ Bh,
    const __half* __restrict__ Bl, float* __restrict__ Cf,
    const __half* __restrict__ Gb16, const int* __restrict__ gidx,
    __half* __restrict__ Out16, __half* __restrict__ Out2, int M) {
    constexpr int K = KT_;
    constexpr int T = K / 32;

    __shared__ __half sA[2][128 * LDA];
    __shared__ __half sB[2][2][64 * LDA];

    const int tid = threadIdx.x;
    const int lane = tid & 31;
    const int warp = tid >> 5;
    const int wm = warp >> 1;
    const int wn = warp & 1;
    const int m0 = blockIdx.y * 128;
    const int n0 = blockIdx.x * 64;

    float acc[2][4][4];
#pragma unroll
    for (int i = 0; i < 2; i++)
#pragma unroll
        for (int j = 0; j < 4; j++)
#pragma unroll
            for (int q = 0; q < 4; q++) acc[i][j][q] = 0.f;

    uint32_t aB[2], bB[2][2];
#pragma unroll
    for (int st = 0; st < 2; st++) {
        aB[st] = (uint32_t)__cvta_generic_to_shared(&sA[st][0]);
#pragma unroll
        for (int hl = 0; hl < 2; hl++)
            bB[st][hl] = (uint32_t)__cvta_generic_to_shared(&sB[st][hl][0]);
    }

    const int a_r0 = tid >> 2;
    const int a_kc = (tid & 3) * 8;
    const int b_r = tid >> 2;
    const int b_kc = (tid & 3) * 8;

    const int a_row = ((lane >> 3) & 1) * 8 + (lane & 7);
    const int a_kof = (lane >> 4) * 8;
    const int b_row = ((lane >> 4) & 1) * 8 + (lane & 7);
    const int b_kof = ((lane >> 3) & 1) * 8;

    const bool pA0 = (m0 + a_r0) < M;
    const bool pA1 = (m0 + a_r0 + 64) < M;
    const uint32_t aOff0 = (uint32_t)(a_r0 * LDA + a_kc) * 2u;
    const uint32_t aOff1 = (uint32_t)((a_r0 + 64) * LDA + a_kc) * 2u;
    const uint32_t bOff = (uint32_t)(b_r * LDA + b_kc) * 2u;
    const __half* gA0 = A + (pA0 ? (long)(m0 + a_r0) * K + a_kc : 0);
    const __half* gA1 = A + (pA1 ? (long)(m0 + a_r0 + 64) * K + a_kc : 0);
    const __half* gBh = Bh + (long)(n0 + b_r) * K + b_kc;
    const __half* gBl = Bl + (long)(n0 + b_r) * K + b_kc;

#define LOAD_STAGE(st, k0)                           \
    do {                                             \
        cp16(aB[st] + aOff0, gA0 + (k0), pA0);       \
        cp16(aB[st] + aOff1, gA1 + (k0), pA1);       \
        cp16(bB[st][0] + bOff, gBh + (k0), true);    \
        cp16(bB[st][1] + bOff, gBl + (k0), true);    \
        cp_commit();                                 \
    } while (0)

    LOAD_STAGE(0, 0);

#pragma unroll
    for (int kt = 0; kt < T; kt++) {
        if (kt + 1 < T) {
            LOAD_STAGE((kt + 1) & 1, (kt + 1) * 32);
            cp_wait<1>();
        } else {
            cp_wait<0>();
        }
        __syncthreads();

        const int st = kt & 1;
#pragma unroll
        for (int ks = 0; ks < 32; ks += 16) {
            uint32_t fa[2][4], fbh[2][4], fbl[2][4];
#pragma unroll
            for (int mt = 0; mt < 2; mt++) {
                uint32_t off = (uint32_t)((wm * 32 + mt * 16 + a_row) * LDA + ks + a_kof) * 2u;
                ldm_x4(aB[st] + off, fa[mt]);
            }
#pragma unroll
            for (int np = 0; np < 2; np++) {
                uint32_t off = (uint32_t)((wn * 32 + np * 16 + b_row) * LDA + ks + b_kof) * 2u;
                ldm_x4(bB[st][0] + off, fbh[np]);
                ldm_x4(bB[st][1] + off, fbl[np]);
            }
#pragma unroll
            for (int term = 0; term < 2; term++) {
#pragma unroll
                for (int mt = 0; mt < 2; mt++) {
#pragma unroll
                    for (int nt = 0; nt < 4; nt++) {
                        uint32_t b0, b1;
                        if (term == 0) {
                            b0 = fbh[nt >> 1][(nt & 1) * 2];
                            b1 = fbh[nt >> 1][(nt & 1) * 2 + 1];
                        } else {
                            b0 = fbl[nt >> 1][(nt & 1) * 2];
                            b1 = fbl[nt >> 1][(nt & 1) * 2 + 1];
                        }
                        mma_f16(acc[mt][nt], fa[mt], b0, b1);
                    }
                }
            }
        }
        __syncthreads();
    }
#undef LOAD_STAGE

    // epilogue
#pragma unroll
    for (int mt = 0; mt < 2; mt++) {
#pragma unroll
        for (int nt = 0; nt < 4; nt++) {
            int rbase = m0 + wm * 32 + mt * 16 + (lane >> 2);
            int col = n0 + wn * 32 + nt * 8 + (lane & 3) * 2;
            float* c = acc[mt][nt];
#pragma unroll
            for (int half = 0; half < 2; half++) {
                int row = rbase + half * 8;
                if (row >= M) continue;
                float v0 = c[half * 2], v1 = c[half * 2 + 1];
                if (EPI == 4 && n0 < 256) {
                    long base = (long)row * 256 + col;
                    *reinterpret_cast<__half2*>(&Out16[base]) =
                        __floats2half2_rn(sp_(v0), sp_(v1));
                } else if (EPI == 4) {
                    long base = (long)row * HD + (col - 256);
                    *reinterpret_cast<__half2*>(&Out2[base]) =
                        __floats2half2_rn(sigm_(v0), sigm_(v1));
                } else if (EPI == 2) {
                    long base = (long)row * HD + col;
                    float2 g2 = __half22float2(
                        *reinterpret_cast<const __half2*>(&Gb16[base]));
                    *reinterpret_cast<__half2*>(&Out16[base]) =
                        __floats2half2_rn(g2.x * sp_(v0), g2.y * sp_(v1));
                } else {  // EPI == 3
                    int seg = gidx[row];
                    atomicAdd(reinterpret_cast<float2*>(&Cf[(long)seg * HD + col]),
                              make_float2(v0, v1));
                }
            }
        }
    }
}

// ---- edge scatter: agg[tgt] += M[src] (fp16 read, fp32 float4 atomics) ----
__global__ void k_scatter(const int* __restrict__ src, const int* __restrict__ tgt) {
    long i = (long)blockIdx.x * blockDim.x + threadIdx.x;
    if (i >= (long)NE * (HD / 4)) return;
    int e = (int)(i >> 5);
    int c = (int)(i & 31);
    int s = src[e], t = tgt[e];
    const __half2* mp = reinterpret_cast<const __half2*>(&g_M[(long)s * HD + c * 4]);
    float2 a = __half22float2(mp[0]);
    float2 b = __half22float2(mp[1]);
    atomicAdd(reinterpret_cast<float4*>(&g_agg[(long)t * HD + c * 4]),
              make_float4(a.x, a.y, b.x, b.y));
}

// ---- node update: x += sp(agg); refresh fp16 copy; zero agg ----
__global__ void k_update() {
    int i = blockIdx.x * blockDim.x + threadIdx.x;
    if (i >= NN * (HD / 4)) return;
    float4 a = ((float4*)g_agg)[i];
    float4 x = ((float4*)g_x)[i];
    x.x += sp_(a.x);
    x.y += sp_(a.y);
    x.z += sp_(a.z);
    x.w += sp_(a.w);
    ((float4*)g_x)[i] = x;
    ((__half2*)g_xf)[i * 2] = __floats2half2_rn(x.x, x.y);
    ((__half2*)g_xf)[i * 2 + 1] = __floats2half2_rn(x.z, x.w);
    ((float4*)g_agg)[i] = make_float4(0.f, 0.f, 0.f, 0.f);
}

__global__ void k_mlp(const float* __restrict__ counts,
                      const float* __restrict__ Wfc1, const float* __restrict__ bfc1,
                      const float* __restrict__ Wfc2, const float* __restrict__ bfc2,
                      const float* __restrict__ Wr, const float* __restrict__ br,
                      float* __restrict__ out) {
    __shared__ float s0[HD];
    __shared__ float s1[HD];
    __shared__ float red[HD];
    int g = blockIdx.x, t = threadIdx.x;

    float yv = g_y[g * HD + t] / counts[g];
    s0[t] = sp_(yv);
    __syncthreads();

    float acc = bfc1[t];
#pragma unroll 8
    for (int k = 0; k < HD; k++) acc += s0[k] * Wfc1[k * HD + t];
    s1[t] = sp_(acc);
    __syncthreads();

    acc = bfc2[t];
#pragma unroll 8
    for (int k = 0; k < HD; k++) acc += s1[k] * Wfc2[k * HD + t];
    float h2 = sp_(acc);

    red[t] = h2 * Wr[t];
    __syncthreads();
    for (int s = HD / 2; s > 0; s >>= 1) {
        if (t < s) red[t] += red[t + s];
        __syncthreads();
    }
    if (t == 0) out[g] = red[0] + br[0];
}

extern "C" void kernel_launch(void* const* d_in, const int* in_sizes, int n_in,
                              void* d_out, int out_size) {
    const int* nodes = (const int*)d_in[0];
    const int* esrc = (const int*)d_in[1];
    const int* etgt = (const int*)d_in[2];
    const int* gidx = (const int*)d_in[3];
    const float* counts = (const float*)d_in[4];
    const float* embed = (const float*)d_in[5];
    const float* Wg = (const float*)d_in[6];
    const float* We1 = (const float*)d_in[7];
    const float* We2 = (const float*)d_in[8];
    const float* Wp = (const float*)d_in[9];
    const float* Wfc1 = (const float*)d_in[10];
    const float* bfc1 = (const float*)d_in[11];
    const float* Wfc2 = (const float*)d_in[12];
    const float* bfc2 = (const float*)d_in[13];
    const float* Wr = (const float*)d_in[14];
    const float* br = (const float*)d_in[15];
    float* out = (float*)d_out;

    __half *pxf, *pAf, *pWfh, *pWfl, *psG, *pM;
    float *py;
    cudaGetSymbolAddress((void**)&pxf, g_xf);
    cudaGetSymbolAddress((void**)&pAf, g_Af);
    cudaGetSymbolAddress((void**)&pWfh, g_Wfh);
    cudaGetSymbolAddress((void**)&pWfl, g_Wfl);
    cudaGetSymbolAddress((void**)&psG, g_sG);
    cudaGetSymbolAddress((void**)&pM, g_M);
    cudaGetSymbolAddress((void**)&py, g_y);

    const int blocksM = (NN + 127) / 128;

    k_wsplit_all<<<(262144 + 255) / 256, 256>>>(Wg, We1, We2, Wp);
    k_zero_y<<<(NG * HD / 4 + 255) / 256, 256>>>();
    {
        int n = NN * (HD / 4);
        k_embed<<<(n + 255) / 256, 256>>>(nodes, embed);
    }
    for (int i = 0; i < NCONV; i++) {
        // merged: sp(x@We1) -> Af (n-tiles 0..3) AND sigmoid(x@Wg) -> sG (4,5)
        k_g16<4, 384, HD><<<dim3(384 / 64, blocksM), 256>>>(
            pxf, pWfh + WCAT(i), pWfl + WCAT(i),
            nullptr, nullptr, nullptr, pAf, psG, NN);
        // M = sG * sp(A @ We2)   (fp16 out)
        k_g16<2, HD, EF><<<dim3(HD / 64, blocksM), 256>>>(
            pAf, pWfh + WE2(i), pWfl + WE2(i),
            nullptr, psG, nullptr, pM, nullptr, NN);
        {
            long n = (long)NE * (HD / 4);
            k_scatter<<<(int)((n + 255) / 256), 256>>>(esrc, etgt);
        }
        {
            int n = NN * (HD / 4);
            k_update<<<(n + 255) / 256, 256>>>();
        }
    }
    // pooling with fused segment atomics (fp32)
    k_g16<3, HD, HD><<<dim3(HD / 64, blocksM), 256>>>(
        pxf, pWfh + WPT, pWfl + WPT,
        py, nullptr, gidx, nullptr, nullptr, NN);
    k_mlp<<<NG, HD>>>(counts, Wfc1, bfc1, Wfc2, bfc2, Wr, br, out);
}

// round 12
// speedup vs baseline: 1.6307x; 1.1773x over previous
#include <cuda_runtime.h>
#include <cuda_bf16.h>
#include <cuda_fp16.h>
#include <cstdint>
#include <math.h>

#define NN 100000
#define NE 600000
#define NG 512
#define HD 128
#define EF 256
#define NCONV 3

// ---- scratch (device globals) ----
__device__ float g_x[NN * HD];        // fp32 master node features
__device__ __half g_xf[NN * HD];      // fp16 MMA copy
__device__ __half g_Af[NN * EF];      // sp(x@We1) fp16
__device__ __half g_sG[NN * HD];      // sigmoid gate fp16
__device__ __half g_M[NN * HD];       // message fp16
__device__ float g_y[NG * HD];
// CSR by target
__device__ int g_cnt[NN];
__device__ int g_cur[NN];
__device__ int g_off[NN + 1];
__device__ int g_elist[NE];
// fp16 split-2 weights
#define WCAT(c) ((c) * 49152)
#define WPT 147456
#define WE2(c) (163840 + (c) * 32768)
__device__ __half g_Wfh[262144];
__device__ __half g_Wfl[262144];

__device__ __forceinline__ float sp_(float x) {
    return fmaxf(x, 0.f) + __logf(1.f + __expf(-fabsf(x)));
}
__device__ __forceinline__ float sigm_(float x) {
    return 1.f / (1.f + __expf(-x));
}

__global__ void k_wsplit_all(const float* __restrict__ Wg, const float* __restrict__ We1,
                             const float* __restrict__ We2, const float* __restrict__ Wp) {
    int i = blockIdx.x * blockDim.x + threadIdx.x;
    if (i >= 262144) return;
    float w;
    if (i < 147456) {
        int c = i / 49152, j = i % 49152;
        int n = j / HD, k = j % HD;
        w = (n < EF) ? We1[c * 32768 + k * EF + n]
                     : Wg[c * 16384 + k * HD + (n - EF)];
    } else if (i < 163840) {
        int j = i - 147456;
        int n = j / HD, k = j % HD;
        w = Wp[k * HD + n];
    } else {
        int j = i - 163840;
        int c = j / 32768, jj = j % 32768;
        int n = jj >> 8, k = jj & 255;
        w = We2[c * 32768 + k * HD + n];
    }
    __half h = __float2half_rn(w);
    __half l = __float2half_rn(w - __half2float(h));
    g_Wfh[i] = h;
    g_Wfl[i] = l;
}

// ---- zero counters + y ----
__global__ void k_zero_misc() {
    int i = blockIdx.x * blockDim.x + threadIdx.x;
    if (i < NN) {
        g_cnt[i] = 0;
        g_cur[i] = 0;
    }
    if (i < NG * HD) g_y[i] = 0.f;
}

// ---- CSR build ----
__global__ void k_hist(const int* __restrict__ tgt) {
    int i = blockIdx.x * blockDim.x + threadIdx.x;
    if (i < NE) atomicAdd(&g_cnt[tgt[i]], 1);
}

// single-block exclusive scan, 1024 threads, 4 elems/thread per chunk
__global__ void k_scan() {
    __shared__ int s[1024];
    __shared__ int carry_s;
    int tid = threadIdx.x;
    if (tid == 0) {
        carry_s = 0;
        g_off[0] = 0;
    }
    __syncthreads();
    for (int base = 0; base < NN; base += 4096) {
        int idx = base + tid * 4;
        int v0 = (idx + 0 < NN) ? g_cnt[idx + 0] : 0;
        int v1 = (idx + 1 < NN) ? g_cnt[idx + 1] : 0;
        int v2 = (idx + 2 < NN) ? g_cnt[idx + 2] : 0;
        int v3 = (idx + 3 < NN) ? g_cnt[idx + 3] : 0;
        int tot = v0 + v1 + v2 + v3;
        s[tid] = tot;
        __syncthreads();
#pragma unroll
        for (int d = 1; d < 1024; d <<= 1) {
            int t = (tid >= d) ? s[tid - d] : 0;
            __syncthreads();
            s[tid] += t;
            __syncthreads();
        }
        int excl = carry_s + s[tid] - tot;
        if (idx + 0 < NN) g_off[idx + 1] = excl + v0;
        if (idx + 1 < NN) g_off[idx + 2] = excl + v0 + v1;
        if (idx + 2 < NN) g_off[idx + 3] = excl + v0 + v1 + v2;
        if (idx + 3 < NN) g_off[idx + 4] = excl + tot;
        __syncthreads();
        if (tid == 0) carry_s += s[1023];
        __syncthreads();
    }
}

__global__ void k_fill(const int* __restrict__ src, const int* __restrict__ tgt) {
    int i = blockIdx.x * blockDim.x + threadIdx.x;
    if (i >= NE) return;
    int t = tgt[i];
    int p = g_off[t] + atomicAdd(&g_cur[t], 1);
    g_elist[p] = src[i];
}

__global__ void k_embed(const int* __restrict__ nodes, const float* __restrict__ embed) {
    int i = blockIdx.x * blockDim.x + threadIdx.x;
    if (i >= NN * (HD / 4)) return;
    int node = nodes[i >> 5];
    float4 v = ((const float4*)embed)[node * 32 + (i & 31)];
    ((float4*)g_x)[i] = v;
    ((__half2*)g_xf)[i * 2] = __floats2half2_rn(v.x, v.y);
    ((__half2*)g_xf)[i * 2 + 1] = __floats2half2_rn(v.z, v.w);
}

// ---- PTX helpers ----
#define LDA 40

__device__ __forceinline__ void cp16(uint32_t dst, const void* src, bool pred) {
    int sz = pred ? 16 : 0;
    asm volatile("cp.async.cg.shared.global [%0], [%1], 16, %2;"
                 :: "r"(dst), "l"(src), "r"(sz));
}
__device__ __forceinline__ void cp_commit() {
    asm volatile("cp.async.commit_group;");
}
template <int N_>
__device__ __forceinline__ void cp_wait() {
    asm volatile("cp.async.wait_group %0;" :: "n"(N_));
}
__device__ __forceinline__ void ldm_x4(uint32_t addr, uint32_t r[4]) {
    asm volatile("ldmatrix.sync.aligned.m8n8.x4.shared.b16 {%0,%1,%2,%3},[%4];"
                 : "=r"(r[0]), "=r"(r[1]), "=r"(r[2]), "=r"(r[3]) : "r"(addr));
}
__device__ __forceinline__ void mma_f16(float c[4], const uint32_t a[4],
                                        uint32_t b0, uint32_t b1) {
    asm volatile(
        "mma.sync.aligned.m16n8k16.row.col.f32.f16.f16.f32 "
        "{%0,%1,%2,%3},{%4,%5,%6,%7},{%8,%9},{%0,%1,%2,%3};"
        : "+f"(c[0]), "+f"(c[1]), "+f"(c[2]), "+f"(c[3])
        : "r"(a[0]), "r"(a[1]), "r"(a[2]), "r"(a[3]), "r"(b0), "r"(b1));
}

// ======================================================================
// Unified fp16 2-term GEMM (same engine as R10/R11).
// EPI: 2 Out16 = Gb16*softplus ; 3 atomicAdd Cf[gidx] ;
//      4 merged (Af softplus | sG sigmoid)
// ======================================================================
template <int EPI, int NT_, int KT_>
__global__ void __launch_bounds__(256) k_g16(
    const __half* __restrict__ A, const __half* __restrict__ Bh,
    const __half* __restrict__ Bl, float* __restrict__ Cf,
    const __half* __restrict__ Gb16, const int* __restrict__ gidx,
    __half* __restrict__ Out16, __half* __restrict__ Out2, int M) {
    constexpr int K = KT_;
    constexpr int T = K / 32;

    __shared__ __half sA[2][128 * LDA];
    __shared__ __half sB[2][2][64 * LDA];

    const int tid = threadIdx.x;
    const int lane = tid & 31;
    const int warp = tid >> 5;
    const int wm = warp >> 1;
    const int wn = warp & 1;
    const int m0 = blockIdx.y * 128;
    const int n0 = blockIdx.x * 64;

    float acc[2][4][4];
#pragma unroll
    for (int i = 0; i < 2; i++)
#pragma unroll
        for (int j = 0; j < 4; j++)
#pragma unroll
            for (int q = 0; q < 4; q++) acc[i][j][q] = 0.f;

    uint32_t aB[2], bB[2][2];
#pragma unroll
    for (int st = 0; st < 2; st++) {
        aB[st] = (uint32_t)__cvta_generic_to_shared(&sA[st][0]);
#pragma unroll
        for (int hl = 0; hl < 2; hl++)
            bB[st][hl] = (uint32_t)__cvta_generic_to_shared(&sB[st][hl][0]);
    }

    const int a_r0 = tid >> 2;
    const int a_kc = (tid & 3) * 8;
    const int b_r = tid >> 2;
    const int b_kc = (tid & 3) * 8;

    const int a_row = ((lane >> 3) & 1) * 8 + (lane & 7);
    const int a_kof = (lane >> 4) * 8;
    const int b_row = ((lane >> 4) & 1) * 8 + (lane & 7);
    const int b_kof = ((lane >> 3) & 1) * 8;

    const bool pA0 = (m0 + a_r0) < M;
    const bool pA1 = (m0 + a_r0 + 64) < M;
    const uint32_t aOff0 = (uint32_t)(a_r0 * LDA + a_kc) * 2u;
    const uint32_t aOff1 = (uint32_t)((a_r0 + 64) * LDA + a_kc) * 2u;
    const uint32_t bOff = (uint32_t)(b_r * LDA + b_kc) * 2u;
    const __half* gA0 = A + (pA0 ? (long)(m0 + a_r0) * K + a_kc : 0);
    const __half* gA1 = A + (pA1 ? (long)(m0 + a_r0 + 64) * K + a_kc : 0);
    const __half* gBh = Bh + (long)(n0 + b_r) * K + b_kc;
    const __half* gBl = Bl + (long)(n0 + b_r) * K + b_kc;

#define LOAD_STAGE(st, k0)                           \
    do {                                             \
        cp16(aB[st] + aOff0, gA0 + (k0), pA0);       \
        cp16(aB[st] + aOff1, gA1 + (k0), pA1);       \
        cp16(bB[st][0] + bOff, gBh + (k0), true);    \
        cp16(bB[st][1] + bOff, gBl + (k0), true);    \
        cp_commit();                                 \
    } while (0)

    LOAD_STAGE(0, 0);

#pragma unroll
    for (int kt = 0; kt < T; kt++) {
        if (kt + 1 < T) {
            LOAD_STAGE((kt + 1) & 1, (kt + 1) * 32);
            cp_wait<1>();
        } else {
            cp_wait<0>();
        }
        __syncthreads();

        const int st = kt & 1;
#pragma unroll
        for (int ks = 0; ks < 32; ks += 16) {
            uint32_t fa[2][4], fbh[2][4], fbl[2][4];
#pragma unroll
            for (int mt = 0; mt < 2; mt++) {
                uint32_t off = (uint32_t)((wm * 32 + mt * 16 + a_row) * LDA + ks + a_kof) * 2u;
                ldm_x4(aB[st] + off, fa[mt]);
            }
#pragma unroll
            for (int np = 0; np < 2; np++) {
                uint32_t off = (uint32_t)((wn * 32 + np * 16 + b_row) * LDA + ks + b_kof) * 2u;
                ldm_x4(bB[st][0] + off, fbh[np]);
                ldm_x4(bB[st][1] + off, fbl[np]);
            }
#pragma unroll
            for (int term = 0; term < 2; term++) {
#pragma unroll
                for (int mt = 0; mt < 2; mt++) {
#pragma unroll
                    for (int nt = 0; nt < 4; nt++) {
                        uint32_t b0, b1;
                        if (term == 0) {
                            b0 = fbh[nt >> 1][(nt & 1) * 2];
                            b1 = fbh[nt >> 1][(nt & 1) * 2 + 1];
                        } else {
                            b0 = fbl[nt >> 1][(nt & 1) * 2];
                            b1 = fbl[nt >> 1][(nt & 1) * 2 + 1];
                        }
                        mma_f16(acc[mt][nt], fa[mt], b0, b1);
                    }
                }
            }
        }
        __syncthreads();
    }
#undef LOAD_STAGE

#pragma unroll
    for (int mt = 0; mt < 2; mt++) {
#pragma unroll
        for (int nt = 0; nt < 4; nt++) {
            int rbase = m0 + wm * 32 + mt * 16 + (lane >> 2);
            int col = n0 + wn * 32 + nt * 8 + (lane & 3) * 2;
            float* c = acc[mt][nt];
#pragma unroll
            for (int half = 0; half < 2; half++) {
                int row = rbase + half * 8;
                if (row >= M) continue;
                float v0 = c[half * 2], v1 = c[half * 2 + 1];
                if (EPI == 4 && n0 < 256) {
                    long base = (long)row * 256 + col;
                    *reinterpret_cast<__half2*>(&Out16[base]) =
                        __floats2half2_rn(sp_(v0), sp_(v1));
                } else if (EPI == 4) {
                    long base = (long)row * HD + (col - 256);
                    *reinterpret_cast<__half2*>(&Out2[base]) =
                        __floats2half2_rn(sigm_(v0), sigm_(v1));
                } else if (EPI == 2) {
                    long base = (long)row * HD + col;
                    float2 g2 = __half22float2(
                        *reinterpret_cast<const __half2*>(&Gb16[base]));
                    *reinterpret_cast<__half2*>(&Out16[base]) =
                        __floats2half2_rn(g2.x * sp_(v0), g2.y * sp_(v1));
                } else {  // EPI == 3
                    int seg = gidx[row];
                    atomicAdd(reinterpret_cast<float2*>(&Cf[(long)seg * HD + col]),
                              make_float2(v0, v1));
                }
            }
        }
    }
}

// ---- CSR gather + fused node update: x += sp(sum M[src]); refresh xf ----
// warp per node, lane handles 4 features
__global__ void __launch_bounds__(256) k_gather() {
    int warp = (blockIdx.x * 256 + threadIdx.x) >> 5;
    int lane = threadIdx.x & 31;
    if (warp >= NN) return;
    int beg = g_off[warp], end = g_off[warp + 1];

    float4 acc = make_float4(0.f, 0.f, 0.f, 0.f);
    int e = beg;
    for (; e + 1 < end; e += 2) {
        int s0 = g_elist[e], s1 = g_elist[e + 1];
        float2 p0 = *reinterpret_cast<const float2*>(&g_M[(long)s0 * HD + lane * 4]);
        float2 p1 = *reinterpret_cast<const float2*>(&g_M[(long)s1 * HD + lane * 4]);
        const __half2* h0 = reinterpret_cast<const __half2*>(&p0);
        const __half2* h1 = reinterpret_cast<const __half2*>(&p1);
        float2 a0 = __half22float2(h0[0]), b0 = __half22float2(h0[1]);
        float2 a1 = __half22float2(h1[0]), b1 = __half22float2(h1[1]);
        acc.x += a0.x + a1.x;
        acc.y += a0.y + a1.y;
        acc.z += b0.x + b1.x;
        acc.w += b0.y + b1.y;
    }
    if (e < end) {
        int s0 = g_elist[e];
        float2 p0 = *reinterpret_cast<const float2*>(&g_M[(long)s0 * HD + lane * 4]);
        const __half2* h0 = reinterpret_cast<const __half2*>(&p0);
        float2 a0 = __half22float2(h0[0]), b0 = __half22float2(h0[1]);
        acc.x += a0.x;
        acc.y += a0.y;
        acc.z += b0.x;
        acc.w += b0.y;
    }

    int i4 = warp * 32 + lane;
    float4 x = ((float4*)g_x)[i4];
    x.x += sp_(acc.x);
    x.y += sp_(acc.y);
    x.z += sp_(acc.z);
    x.w += sp_(acc.w);
    ((float4*)g_x)[i4] = x;
    ((__half2*)g_xf)[i4 * 2] = __floats2half2_rn(x.x, x.y);
    ((__half2*)g_xf)[i4 * 2 + 1] = __floats2half2_rn(x.z, x.w);
}

__global__ void k_mlp(const float* __restrict__ counts,
                      const float* __restrict__ Wfc1, const float* __restrict__ bfc1,
                      const float* __restrict__ Wfc2, const float* __restrict__ bfc2,
                      const float* __restrict__ Wr, const float* __restrict__ br,
                      float* __restrict__ out) {
    __shared__ float s0[HD];
    __shared__ float s1[HD];
    __shared__ float red[HD];
    int g = blockIdx.x, t = threadIdx.x;

    float yv = g_y[g * HD + t] / counts[g];
    s0[t] = sp_(yv);
    __syncthreads();

    float acc = bfc1[t];
#pragma unroll 8
    for (int k = 0; k < HD; k++) acc += s0[k] * Wfc1[k * HD + t];
    s1[t] = sp_(acc);
    __syncthreads();

    acc = bfc2[t];
#pragma unroll 8
    for (int k = 0; k < HD; k++) acc += s1[k] * Wfc2[k * HD + t];
    float h2 = sp_(acc);

    red[t] = h2 * Wr[t];
    __syncthreads();
    for (int s = HD / 2; s > 0; s >>= 1) {
        if (t < s) red[t] += red[t + s];
        __syncthreads();
    }
    if (t == 0) out[g] = red[0] + br[0];
}

extern "C" void kernel_launch(void* const* d_in, const int* in_sizes, int n_in,
                              void* d_out, int out_size) {
    const int* nodes = (const int*)d_in[0];
    const int* esrc = (const int*)d_in[1];
    const int* etgt = (const int*)d_in[2];
    const int* gidx = (const int*)d_in[3];
    const float* counts = (const float*)d_in[4];
    const float* embed = (const float*)d_in[5];
    const float* Wg = (const float*)d_in[6];
    const float* We1 = (const float*)d_in[7];
    const float* We2 = (const float*)d_in[8];
    const float* Wp = (const float*)d_in[9];
    const float* Wfc1 = (const float*)d_in[10];
    const float* bfc1 = (const float*)d_in[11];
    const float* Wfc2 = (const float*)d_in[12];
    const float* bfc2 = (const float*)d_in[13];
    const float* Wr = (const float*)d_in[14];
    const float* br = (const float*)d_in[15];
    float* out = (float*)d_out;

    __half *pxf, *pAf, *pWfh, *pWfl, *psG, *pM;
    float* py;
    cudaGetSymbolAddress((void**)&pxf, g_xf);
    cudaGetSymbolAddress((void**)&pAf, g_Af);
    cudaGetSymbolAddress((void**)&pWfh, g_Wfh);
    cudaGetSymbolAddress((void**)&pWfl, g_Wfl);
    cudaGetSymbolAddress((void**)&psG, g_sG);
    cudaGetSymbolAddress((void**)&pM, g_M);
    cudaGetSymbolAddress((void**)&py, g_y);

    const int blocksM = (NN + 127) / 128;

    k_wsplit_all<<<(262144 + 255) / 256, 256>>>(Wg, We1, We2, Wp);
    k_zero_misc<<<(NN + 255) / 256, 256>>>();
    k_hist<<<(NE + 255) / 256, 256>>>(etgt);
    k_scan<<<1, 1024>>>();
    k_fill<<<(NE + 255) / 256, 256>>>(esrc, etgt);
    {
        int n = NN * (HD / 4);
        k_embed<<<(n + 255) / 256, 256>>>(nodes, embed);
    }
    for (int i = 0; i < NCONV; i++) {
        // merged: sp(x@We1) -> Af AND sigmoid(x@Wg) -> sG
        k_g16<4, 384, HD><<<dim3(384 / 64, blocksM), 256>>>(
            pxf, pWfh + WCAT(i), pWfl + WCAT(i),
            nullptr, nullptr, nullptr, pAf, psG, NN);
        // M = sG * sp(A @ We2)
        k_g16<2, HD, EF><<<dim3(HD / 64, blocksM), 256>>>(
            pAf, pWfh + WE2(i), pWfl + WE2(i),
            nullptr, psG, nullptr, pM, nullptr, NN);
        // CSR gather + fused update
        k_gather<<<(NN + 7) / 8, 256>>>();
    }
    // pooling with fused segment atomics
    k_g16<3, HD, HD><<<dim3(HD / 64, blocksM), 256>>>(
        pxf, pWfh + WPT, pWfl + WPT,
        py, nullptr, gidx, nullptr, nullptr, NN);
    k_mlp<<<NG, HD>>>(counts, Wfc1, bfc1, Wfc2, bfc2, Wr, br, out);
}

// round 13
// speedup vs baseline: 1.6742x; 1.0267x over previous
#include <cuda_runtime.h>
#include <cuda_bf16.h>
#include <cuda_fp16.h>
#include <cstdint>
#include <math.h>

#define NN 100000
#define NE 600000
#define NG 512
#define HD 128
#define EF 256
#define NCONV 3

// ---- scratch (device globals) ----
__device__ float g_x[NN * HD];        // fp32 master node features
__device__ __half g_xf[NN * HD];      // fp16 MMA copy
__device__ __half g_Af[NN * EF];      // sp(x@We1) fp16
__device__ __half g_sG[NN * HD];      // sigmoid gate fp16
__device__ __half g_M[NN * HD];       // message fp16
__device__ float g_y[NG * HD];
// CSR by target
__device__ int g_cnt[NN];
__device__ int g_cur[NN];
__device__ int g_off[NN + 1];
__device__ int g_elist[NE];
// fp16 split-2 weights
#define WCAT(c) ((c) * 49152)
#define WPT 147456
#define WE2(c) (163840 + (c) * 32768)
__device__ __half g_Wfh[262144];
__device__ __half g_Wfl[262144];

__device__ __forceinline__ float sp_(float x) {
    return fmaxf(x, 0.f) + __logf(1.f + __expf(-fabsf(x)));
}
__device__ __forceinline__ float sigm_(float x) {
    return 1.f / (1.f + __expf(-x));
}

__global__ void k_wsplit_all(const float* __restrict__ Wg, const float* __restrict__ We1,
                             const float* __restrict__ We2, const float* __restrict__ Wp) {
    int i = blockIdx.x * blockDim.x + threadIdx.x;
    if (i >= 262144) return;
    float w;
    if (i < 147456) {
        int c = i / 49152, j = i % 49152;
        int n = j / HD, k = j % HD;
        w = (n < EF) ? We1[c * 32768 + k * EF + n]
                     : Wg[c * 16384 + k * HD + (n - EF)];
    } else if (i < 163840) {
        int j = i - 147456;
        int n = j / HD, k = j % HD;
        w = Wp[k * HD + n];
    } else {
        int j = i - 163840;
        int c = j / 32768, jj = j % 32768;
        int n = jj >> 8, k = jj & 255;
        w = We2[c * 32768 + k * HD + n];
    }
    __half h = __float2half_rn(w);
    __half l = __float2half_rn(w - __half2float(h));
    g_Wfh[i] = h;
    g_Wfl[i] = l;
}

// ---- zero counters + y ----
__global__ void k_zero_misc() {
    int i = blockIdx.x * blockDim.x + threadIdx.x;
    if (i < NN) {
        g_cnt[i] = 0;
        g_cur[i] = 0;
    }
    if (i < NG * HD) g_y[i] = 0.f;
}

// ---- CSR build ----
__global__ void k_hist(const int* __restrict__ tgt) {
    int i = blockIdx.x * blockDim.x + threadIdx.x;
    if (i < NE) atomicAdd(&g_cnt[tgt[i]], 1);
}

// single-block exclusive scan, warp-shuffle based (2 barriers per 4096 chunk)
__global__ void k_scan() {
    __shared__ int wsum[32];
    __shared__ int carry_s;
    const int tid = threadIdx.x;
    const int lane = tid & 31;
    const int wid = tid >> 5;
    if (tid == 0) {
        carry_s = 0;
        g_off[0] = 0;
    }
    __syncthreads();
    for (int base = 0; base < NN; base += 4096) {
        int idx = base + tid * 4;
        int v0 = (idx + 0 < NN) ? g_cnt[idx + 0] : 0;
        int v1 = (idx + 1 < NN) ? g_cnt[idx + 1] : 0;
        int v2 = (idx + 2 < NN) ? g_cnt[idx + 2] : 0;
        int v3 = (idx + 3 < NN) ? g_cnt[idx + 3] : 0;
        int tot = v0 + v1 + v2 + v3;

        // warp inclusive scan of tot
        int inc = tot;
#pragma unroll
        for (int d = 1; d < 32; d <<= 1) {
            int t = __shfl_up_sync(0xFFFFFFFFu, inc, d);
            if (lane >= d) inc += t;
        }
        if (lane == 31) wsum[wid] = inc;
        __syncthreads();
        if (wid == 0) {
            int w = wsum[lane];
            int wi = w;
#pragma unroll
            for (int d = 1; d < 32; d <<= 1) {
                int t = __shfl_up_sync(0xFFFFFFFFu, wi, d);
                if (lane >= d) wi += t;
            }
            wsum[lane] = wi - w;  // exclusive
        }
        __syncthreads();
        int excl = carry_s + wsum[wid] + inc - tot;

        if (idx + 0 < NN) g_off[idx + 1] = excl + v0;
        if (idx + 1 < NN) g_off[idx + 2] = excl + v0 + v1;
        if (idx + 2 < NN) g_off[idx + 3] = excl + v0 + v1 + v2;
        if (idx + 3 < NN) g_off[idx + 4] = excl + tot;
        __syncthreads();
        if (tid == 1023) carry_s += wsum[31] + inc;  // wsum[31] excl + last warp's inc = chunk total... careful
        __syncthreads();
    }
}

__global__ void k_fill(const int* __restrict__ src, const int* __restrict__ tgt) {
    int i = blockIdx.x * blockDim.x + threadIdx.x;
    if (i >= NE) return;
    int t = tgt[i];
    int p = g_off[t] + atomicAdd(&g_cur[t], 1);
    g_elist[p] = src[i];
}

__global__ void k_embed(const int* __restrict__ nodes, const float* __restrict__ embed) {
    int i = blockIdx.x * blockDim.x + threadIdx.x;
    if (i >= NN * (HD / 4)) return;
    int node = nodes[i >> 5];
    float4 v = ((const float4*)embed)[node * 32 + (i & 31)];
    ((float4*)g_x)[i] = v;
    ((__half2*)g_xf)[i * 2] = __floats2half2_rn(v.x, v.y);
    ((__half2*)g_xf)[i * 2 + 1] = __floats2half2_rn(v.z, v.w);
}

// ---- PTX helpers ----
#define LDA 40

__device__ __forceinline__ void cp16(uint32_t dst, const void* src, bool pred) {
    int sz = pred ? 16 : 0;
    asm volatile("cp.async.cg.shared.global [%0], [%1], 16, %2;"
                 :: "r"(dst), "l"(src), "r"(sz));
}
__device__ __forceinline__ void cp_commit() {
    asm volatile("cp.async.commit_group;");
}
template <int N_>
__device__ __forceinline__ void cp_wait() {
    asm volatile("cp.async.wait_group %0;" :: "n"(N_));
}
__device__ __forceinline__ void ldm_x4(uint32_t addr, uint32_t r[4]) {
    asm volatile("ldmatrix.sync.aligned.m8n8.x4.shared.b16 {%0,%1,%2,%3},[%4];"
                 : "=r"(r[0]), "=r"(r[1]), "=r"(r[2]), "=r"(r[3]) : "r"(addr));
}
__device__ __forceinline__ void mma_f16(float c[4], const uint32_t a[4],
                                        uint32_t b0, uint32_t b1) {
    asm volatile(
        "mma.sync.aligned.m16n8k16.row.col.f32.f16.f16.f32 "
        "{%0,%1,%2,%3},{%4,%5,%6,%7},{%8,%9},{%0,%1,%2,%3};"
        : "+f"(c[0]), "+f"(c[1]), "+f"(c[2]), "+f"(c[3])
        : "r"(a[0]), "r"(a[1]), "r"(a[2]), "r"(a[3]), "r"(b0), "r"(b1));
}

// ======================================================================
// Unified fp16 2-term GEMM.
// EPI: 2 Out16 = Gb16*softplus ; 3 atomicAdd Cf[gidx] ;
//      4 merged (Af softplus | sG sigmoid)
// ======================================================================
template <int EPI, int NT_, int KT_>
__global__ void __launch_bounds__(256) k_g16(
    const __half* __restrict__ A, const __half* __restrict__ Bh,
    const __half* __restrict__ Bl, float* __restrict__ Cf,
    const __half* __restrict__ Gb16, const int* __restrict__ gidx,
    __half* __restrict__ Out16, __half* __restrict__ Out2, int M) {
    constexpr int K = KT_;
    constexpr int T = K / 32;

    __shared__ __half sA[2][128 * LDA];
    __shared__ __half sB[2][2][64 * LDA];

    const int tid = threadIdx.x;
    const int lane = tid & 31;
    const int warp = tid >> 5;
    const int wm = warp >> 1;
    const int wn = warp & 1;
    const int m0 = blockIdx.y * 128;
    const int n0 = blockIdx.x * 64;

    float acc[2][4][4];
#pragma unroll
    for (int i = 0; i < 2; i++)
#pragma unroll
        for (int j = 0; j < 4; j++)
#pragma unroll
            for (int q = 0; q < 4; q++) acc[i][j][q] = 0.f;

    uint32_t aB[2], bB[2][2];
#pragma unroll
    for (int st = 0; st < 2; st++) {
        aB[st] = (uint32_t)__cvta_generic_to_shared(&sA[st][0]);
#pragma unroll
        for (int hl = 0; hl < 2; hl++)
            bB[st][hl] = (uint32_t)__cvta_generic_to_shared(&sB[st][hl][0]);
    }

    const int a_r0 = tid >> 2;
    const int a_kc = (tid & 3) * 8;
    const int b_r = tid >> 2;
    const int b_kc = (tid & 3) * 8;

    const int a_row = ((lane >> 3) & 1) * 8 + (lane & 7);
    const int a_kof = (lane >> 4) * 8;
    const int b_row = ((lane >> 4) & 1) * 8 + (lane & 7);
    const int b_kof = ((lane >> 3) & 1) * 8;

    const bool pA0 = (m0 + a_r0) < M;
    const bool pA1 = (m0 + a_r0 + 64) < M;
    const uint32_t aOff0 = (uint32_t)(a_r0 * LDA + a_kc) * 2u;
    const uint32_t aOff1 = (uint32_t)((a_r0 + 64) * LDA + a_kc) * 2u;
    const uint32_t bOff = (uint32_t)(b_r * LDA + b_kc) * 2u;
    const __half* gA0 = A + (pA0 ? (long)(m0 + a_r0) * K + a_kc : 0);
    const __half* gA1 = A + (pA1 ? (long)(m0 + a_r0 + 64) * K + a_kc : 0);
    const __half* gBh = Bh + (long)(n0 + b_r) * K + b_kc;
    const __half* gBl = Bl + (long)(n0 + b_r) * K + b_kc;

#define LOAD_STAGE(st, k0)                           \
    do {                                             \
        cp16(aB[st] + aOff0, gA0 + (k0), pA0);       \
        cp16(aB[st] + aOff1, gA1 + (k0), pA1);       \
        cp16(bB[st][0] + bOff, gBh + (k0), true);    \
        cp16(bB[st][1] + bOff, gBl + (k0), true);    \
        cp_commit();                                 \
    } while (0)

    LOAD_STAGE(0, 0);

#pragma unroll
    for (int kt = 0; kt < T; kt++) {
        if (kt + 1 < T) {
            LOAD_STAGE((kt + 1) & 1, (kt + 1) * 32);
            cp_wait<1>();
        } else {
            cp_wait<0>();
        }
        __syncthreads();

        const int st = kt & 1;
#pragma unroll
        for (int ks = 0; ks < 32; ks += 16) {
            uint32_t fa[2][4], fbh[2][4], fbl[2][4];
#pragma unroll
            for (int mt = 0; mt < 2; mt++) {
                uint32_t off = (uint32_t)((wm * 32 + mt * 16 + a_row) * LDA + ks + a_kof) * 2u;
                ldm_x4(aB[st] + off, fa[mt]);
            }
#pragma unroll
            for (int np = 0; np < 2; np++) {
                uint32_t off = (uint32_t)((wn * 32 + np * 16 + b_row) * LDA + ks + b_kof) * 2u;
                ldm_x4(bB[st][0] + off, fbh[np]);
                ldm_x4(bB[st][1] + off, fbl[np]);
            }
#pragma unroll
            for (int term = 0; term < 2; term++) {
#pragma unroll
                for (int mt = 0; mt < 2; mt++) {
#pragma unroll
                    for (int nt = 0; nt < 4; nt++) {
                        uint32_t b0, b1;
                        if (term == 0) {
                            b0 = fbh[nt >> 1][(nt & 1) * 2];
                            b1 = fbh[nt >> 1][(nt & 1) * 2 + 1];
                        } else {
                            b0 = fbl[nt >> 1][(nt & 1) * 2];
                            b1 = fbl[nt >> 1][(nt & 1) * 2 + 1];
                        }
                        mma_f16(acc[mt][nt], fa[mt], b0, b1);
                    }
                }
            }
        }
        __syncthreads();
    }
#undef LOAD_STAGE

#pragma unroll
    for (int mt = 0; mt < 2; mt++) {
#pragma unroll
        for (int nt = 0; nt < 4; nt++) {
            int rbase = m0 + wm * 32 + mt * 16 + (lane >> 2);
            int col = n0 + wn * 32 + nt * 8 + (lane & 3) * 2;
            float* c = acc[mt][nt];
#pragma unroll
            for (int half = 0; half < 2; half++) {
                int row = rbase + half * 8;
                if (row >= M) continue;
                float v0 = c[half * 2], v1 = c[half * 2 + 1];
                if (EPI == 4 && n0 < 256) {
                    long base = (long)row * 256 + col;
                    *reinterpret_cast<__half2*>(&Out16[base]) =
                        __floats2half2_rn(sp_(v0), sp_(v1));
                } else if (EPI == 4) {
                    long base = (long)row * HD + (col - 256);
                    *reinterpret_cast<__half2*>(&Out2[base]) =
                        __floats2half2_rn(sigm_(v0), sigm_(v1));
                } else if (EPI == 2) {
                    long base = (long)row * HD + col;
                    float2 g2 = __half22float2(
                        *reinterpret_cast<const __half2*>(&Gb16[base]));
                    *reinterpret_cast<__half2*>(&Out16[base]) =
                        __floats2half2_rn(g2.x * sp_(v0), g2.y * sp_(v1));
                } else {  // EPI == 3
                    int seg = gidx[row];
                    atomicAdd(reinterpret_cast<float2*>(&Cf[(long)seg * HD + col]),
                              make_float2(v0, v1));
                }
            }
        }
    }
}

// ---- CSR gather + fused node update ----
__global__ void __launch_bounds__(256) k_gather() {
    int warp = (blockIdx.x * 256 + threadIdx.x) >> 5;
    int lane = threadIdx.x & 31;
    if (warp >= NN) return;
    int beg = g_off[warp], end = g_off[warp + 1];

    float4 acc = make_float4(0.f, 0.f, 0.f, 0.f);
    int e = beg;
    for (; e + 1 < end; e += 2) {
        int s0 = g_elist[e], s1 = g_elist[e + 1];
        float2 p0 = *reinterpret_cast<const float2*>(&g_M[(long)s0 * HD + lane * 4]);
        float2 p1 = *reinterpret_cast<const float2*>(&g_M[(long)s1 * HD + lane * 4]);
        const __half2* h0 = reinterpret_cast<const __half2*>(&p0);
        const __half2* h1 = reinterpret_cast<const __half2*>(&p1);
        float2 a0 = __half22float2(h0[0]), b0 = __half22float2(h0[1]);
        float2 a1 = __half22float2(h1[0]), b1 = __half22float2(h1[1]);
        acc.x += a0.x + a1.x;
        acc.y += a0.y + a1.y;
        acc.z += b0.x + b1.x;
        acc.w += b0.y + b1.y;
    }
    if (e < end) {
        int s0 = g_elist[e];
        float2 p0 = *reinterpret_cast<const float2*>(&g_M[(long)s0 * HD + lane * 4]);
        const __half2* h0 = reinterpret_cast<const __half2*>(&p0);
        float2 a0 = __half22float2(h0[0]), b0 = __half22float2(h0[1]);
        acc.x += a0.x;
        acc.y += a0.y;
        acc.z += b0.x;
        acc.w += b0.y;
    }

    int i4 = warp * 32 + lane;
    float4 x = ((float4*)g_x)[i4];
    x.x += sp_(acc.x);
    x.y += sp_(acc.y);
    x.z += sp_(acc.z);
    x.w += sp_(acc.w);
    ((float4*)g_x)[i4] = x;
    ((__half2*)g_xf)[i4 * 2] = __floats2half2_rn(x.x, x.y);
    ((__half2*)g_xf)[i4 * 2 + 1] = __floats2half2_rn(x.z, x.w);
}

__global__ void k_mlp(const float* __restrict__ counts,
                      const float* __restrict__ Wfc1, const float* __restrict__ bfc1,
                      const float* __restrict__ Wfc2, const float* __restrict__ bfc2,
                      const float* __restrict__ Wr, const float* __restrict__ br,
                      float* __restrict__ out) {
    __shared__ float s0[HD];
    __shared__ float s1[HD];
    __shared__ float red[HD];
    int g = blockIdx.x, t = threadIdx.x;

    float yv = g_y[g * HD + t] / counts[g];
    s0[t] = sp_(yv);
    __syncthreads();

    float acc = bfc1[t];
#pragma unroll 8
    for (int k = 0; k < HD; k++) acc += s0[k] * Wfc1[k * HD + t];
    s1[t] = sp_(acc);
    __syncthreads();

    acc = bfc2[t];
#pragma unroll 8
    for (int k = 0; k < HD; k++) acc += s1[k] * Wfc2[k * HD + t];
    float h2 = sp_(acc);

    red[t] = h2 * Wr[t];
    __syncthreads();
    for (int s = HD / 2; s > 0; s >>= 1) {
        if (t < s) red[t] += red[t + s];
        __syncthreads();
    }
    if (t == 0) out[g] = red[0] + br[0];
}

extern "C" void kernel_launch(void* const* d_in, const int* in_sizes, int n_in,
                              void* d_out, int out_size) {
    const int* nodes = (const int*)d_in[0];
    const int* esrc = (const int*)d_in[1];
    const int* etgt = (const int*)d_in[2];
    const int* gidx = (const int*)d_in[3];
    const float* counts = (const float*)d_in[4];
    const float* embed = (const float*)d_in[5];
    const float* Wg = (const float*)d_in[6];
    const float* We1 = (const float*)d_in[7];
    const float* We2 = (const float*)d_in[8];
    const float* Wp = (const float*)d_in[9];
    const float* Wfc1 = (const float*)d_in[10];
    const float* bfc1 = (const float*)d_in[11];
    const float* Wfc2 = (const float*)d_in[12];
    const float* bfc2 = (const float*)d_in[13];
    const float* Wr = (const float*)d_in[14];
    const float* br = (const float*)d_in[15];
    float* out = (float*)d_out;

    __half *pxf, *pAf, *pWfh, *pWfl, *psG, *pM;
    float* py;
    cudaGetSymbolAddress((void**)&pxf, g_xf);
    cudaGetSymbolAddress((void**)&pAf, g_Af);
    cudaGetSymbolAddress((void**)&pWfh, g_Wfh);
    cudaGetSymbolAddress((void**)&pWfl, g_Wfl);
    cudaGetSymbolAddress((void**)&psG, g_sG);
    cudaGetSymbolAddress((void**)&pM, g_M);
    cudaGetSymbolAddress((void**)&py, g_y);

    const int blocksM = (NN + 127) / 128;

    k_wsplit_all<<<(262144 + 255) / 256, 256>>>(Wg, We1, We2, Wp);
    k_zero_misc<<<(NN + 255) / 256, 256>>>();
    k_hist<<<(NE + 255) / 256, 256>>>(etgt);
    k_scan<<<1, 1024>>>();
    k_fill<<<(NE + 255) / 256, 256>>>(esrc, etgt);
    {
        int n = NN * (HD / 4);
        k_embed<<<(n + 255) / 256, 256>>>(nodes, embed);
    }
    for (int i = 0; i < NCONV; i++) {
        k_g16<4, 384, HD><<<dim3(384 / 64, blocksM), 256>>>(
            pxf, pWfh + WCAT(i), pWfl + WCAT(i),
            nullptr, nullptr, nullptr, pAf, psG, NN);
        k_g16<2, HD, EF><<<dim3(HD / 64, blocksM), 256>>>(
            pAf, pWfh + WE2(i), pWfl + WE2(i),
            nullptr, psG, nullptr, pM, nullptr, NN);
        k_gather<<<(NN + 7) / 8, 256>>>();
    }
    k_g16<3, HD, HD><<<dim3(HD / 64, blocksM), 256>>>(
        pxf, pWfh + WPT, pWfl + WPT,
        py, nullptr, gidx, nullptr, nullptr, NN);
    k_mlp<<<NG, HD>>>(counts, Wfc1, bfc1, Wfc2, bfc2, Wr, br, out);
}

// round 14
// speedup vs baseline: 1.7584x; 1.0503x over previous
#include <cuda_runtime.h>
#include <cuda_bf16.h>
#include <cuda_fp16.h>
#include <cstdint>
#include <math.h>

#define NN 100000
#define NE 600000
#define NG 512
#define HD 128
#define EF 256
#define NCONV 3
#define NB_SCAN 98  // ceil(NN/1024)

// ---- scratch (device globals) ----
__device__ float g_x[NN * HD];
__device__ __half g_xf[NN * HD];
__device__ __half g_Af[NN * EF];
__device__ __half g_sG[NN * HD];
__device__ __half g_M[NN * HD];
__device__ float g_y[NG * HD];
// CSR by target
__device__ int g_cnt[NN];
__device__ int g_cur[NN];
__device__ int g_off[NN + 1];
__device__ int g_elist[NE];
__device__ int g_bsum[128];
__device__ int g_bpre[128];
// fp16 split-2 weights
#define WCAT(c) ((c) * 49152)
#define WPT 147456
#define WE2(c) (163840 + (c) * 32768)
__device__ __half g_Wfh[262144];
__device__ __half g_Wfl[262144];

__device__ __forceinline__ float sp_(float x) {
    return fmaxf(x, 0.f) + __logf(1.f + __expf(-fabsf(x)));
}
__device__ __forceinline__ float sigm_(float x) {
    return 1.f / (1.f + __expf(-x));
}

__global__ void k_wsplit_all(const float* __restrict__ Wg, const float* __restrict__ We1,
                             const float* __restrict__ We2, const float* __restrict__ Wp) {
    int i = blockIdx.x * blockDim.x + threadIdx.x;
    if (i >= 262144) return;
    float w;
    if (i < 147456) {
        int c = i / 49152, j = i % 49152;
        int n = j / HD, k = j % HD;
        w = (n < EF) ? We1[c * 32768 + k * EF + n]
                     : Wg[c * 16384 + k * HD + (n - EF)];
    } else if (i < 163840) {
        int j = i - 147456;
        int n = j / HD, k = j % HD;
        w = Wp[k * HD + n];
    } else {
        int j = i - 163840;
        int c = j / 32768, jj = j % 32768;
        int n = jj >> 8, k = jj & 255;
        w = We2[c * 32768 + k * HD + n];
    }
    __half h = __float2half_rn(w);
    __half l = __float2half_rn(w - __half2float(h));
    g_Wfh[i] = h;
    g_Wfl[i] = l;
}

__global__ void k_zero_misc() {
    int i = blockIdx.x * blockDim.x + threadIdx.x;
    if (i < NN) {
        g_cnt[i] = 0;
        g_cur[i] = 0;
    }
    if (i < NG * HD) g_y[i] = 0.f;
}

__global__ void k_hist(const int* __restrict__ tgt) {
    int i = blockIdx.x * blockDim.x + threadIdx.x;
    if (i < NE) atomicAdd(&g_cnt[tgt[i]], 1);
}

// ---- 3-phase parallel scan ----
__global__ void k_scan1() {
    __shared__ int wsum[32];
    const int tid = threadIdx.x;
    const int lane = tid & 31;
    const int wid = tid >> 5;
    const int i = blockIdx.x * 1024 + tid;
    int v = (i < NN) ? g_cnt[i] : 0;
    int inc = v;
#pragma unroll
    for (int d = 1; d < 32; d <<= 1) {
        int t = __shfl_up_sync(0xFFFFFFFFu, inc, d);
        if (lane >= d) inc += t;
    }
    if (lane == 31) wsum[wid] = inc;
    __syncthreads();
    if (wid == 0) {
        int w = wsum[lane];
        int wi = w;
#pragma unroll
        for (int d = 1; d < 32; d <<= 1) {
            int t = __shfl_up_sync(0xFFFFFFFFu, wi, d);
            if (lane >= d) wi += t;
        }
        wsum[lane] = wi - w;
    }
    __syncthreads();
    int binc = wsum[wid] + inc;  // block-local inclusive
    if (i < NN) g_off[i + 1] = binc;
    if (tid == 1023) g_bsum[blockIdx.x] = binc;
}

__global__ void k_scan2() {
    __shared__ int ws[4];
    const int tid = threadIdx.x;  // 128
    const int lane = tid & 31;
    const int wid = tid >> 5;
    int v = (tid < NB_SCAN) ? g_bsum[tid] : 0;
    int inc = v;
#pragma unroll
    for (int d = 1; d < 32; d <<= 1) {
        int t = __shfl_up_sync(0xFFFFFFFFu, inc, d);
        if (lane >= d) inc += t;
    }
    if (lane == 31) ws[wid] = inc;
    __syncthreads();
    if (tid == 0) {
        int a = 0;
#pragma unroll
        for (int w = 0; w < 4; w++) {
            int t = ws[w];
            ws[w] = a;
            a += t;
        }
    }
    __syncthreads();
    if (tid < NB_SCAN) g_bpre[tid] = ws[wid] + inc - v;  // exclusive prefix
}

__global__ void k_scan3() {
    int i = blockIdx.x * blockDim.x + threadIdx.x;
    if (i == 0) g_off[0] = 0;
    if (i < NN) g_off[i + 1] += g_bpre[i >> 10];
}

__global__ void k_fill(const int* __restrict__ src, const int* __restrict__ tgt) {
    int i = blockIdx.x * blockDim.x + threadIdx.x;
    if (i >= NE) return;
    int t = tgt[i];
    int p = g_off[t] + atomicAdd(&g_cur[t], 1);
    g_elist[p] = src[i];
}

__global__ void k_embed(const int* __restrict__ nodes, const float* __restrict__ embed) {
    int i = blockIdx.x * blockDim.x + threadIdx.x;
    if (i >= NN * (HD / 4)) return;
    int node = nodes[i >> 5];
    float4 v = ((const float4*)embed)[node * 32 + (i & 31)];
    ((float4*)g_x)[i] = v;
    ((__half2*)g_xf)[i * 2] = __floats2half2_rn(v.x, v.y);
    ((__half2*)g_xf)[i * 2 + 1] = __floats2half2_rn(v.z, v.w);
}

// ---- PTX helpers ----
#define LDA 40

__device__ __forceinline__ void cp16(uint32_t dst, const void* src, bool pred) {
    int sz = pred ? 16 : 0;
    asm volatile("cp.async.cg.shared.global [%0], [%1], 16, %2;"
                 :: "r"(dst), "l"(src), "r"(sz));
}
__device__ __forceinline__ void cp_commit() {
    asm volatile("cp.async.commit_group;");
}
template <int N_>
__device__ __forceinline__ void cp_wait() {
    asm volatile("cp.async.wait_group %0;" :: "n"(N_));
}
__device__ __forceinline__ void ldm_x4(uint32_t addr, uint32_t r[4]) {
    asm volatile("ldmatrix.sync.aligned.m8n8.x4.shared.b16 {%0,%1,%2,%3},[%4];"
                 : "=r"(r[0]), "=r"(r[1]), "=r"(r[2]), "=r"(r[3]) : "r"(addr));
}
__device__ __forceinline__ void mma_f16(float c[4], const uint32_t a[4],
                                        uint32_t b0, uint32_t b1) {
    asm volatile(
        "mma.sync.aligned.m16n8k16.row.col.f32.f16.f16.f32 "
        "{%0,%1,%2,%3},{%4,%5,%6,%7},{%8,%9},{%0,%1,%2,%3};"
        : "+f"(c[0]), "+f"(c[1]), "+f"(c[2]), "+f"(c[3])
        : "r"(a[0]), "r"(a[1]), "r"(a[2]), "r"(a[3]), "r"(b0), "r"(b1));
}

// ======================================================================
// Unified fp16 2-term GEMM.
// EPI: 2 Out16 = Gb16*softplus ; 3 atomicAdd Cf[gidx] ;
//      4 merged (Af softplus | sG sigmoid)
// ======================================================================
template <int EPI, int NT_, int KT_>
__global__ void __launch_bounds__(256) k_g16(
    const __half* __restrict__ A, const __half* __restrict__ Bh,
    const __half* __restrict__ Bl, float* __restrict__ Cf,
    const __half* __restrict__ Gb16, const int* __restrict__ gidx,
    __half* __restrict__ Out16, __half* __restrict__ Out2, int M) {
    constexpr int K = KT_;
    constexpr int T = K / 32;

    __shared__ __half sA[2][128 * LDA];
    __shared__ __half sB[2][2][64 * LDA];

    const int tid = threadIdx.x;
    const int lane = tid & 31;
    const int warp = tid >> 5;
    const int wm = warp >> 1;
    const int wn = warp & 1;
    const int m0 = blockIdx.y * 128;
    const int n0 = blockIdx.x * 64;

    float acc[2][4][4];
#pragma unroll
    for (int i = 0; i < 2; i++)
#pragma unroll
        for (int j = 0; j < 4; j++)
#pragma unroll
            for (int q = 0; q < 4; q++) acc[i][j][q] = 0.f;

    uint32_t aB[2], bB[2][2];
#pragma unroll
    for (int st = 0; st < 2; st++) {
        aB[st] = (uint32_t)__cvta_generic_to_shared(&sA[st][0]);
#pragma unroll
        for (int hl = 0; hl < 2; hl++)
            bB[st][hl] = (uint32_t)__cvta_generic_to_shared(&sB[st][hl][0]);
    }

    const int a_r0 = tid >> 2;
    const int a_kc = (tid & 3) * 8;
    const int b_r = tid >> 2;
    const int b_kc = (tid & 3) * 8;

    const int a_row = ((lane >> 3) & 1) * 8 + (lane & 7);
    const int a_kof = (lane >> 4) * 8;
    const int b_row = ((lane >> 4) & 1) * 8 + (lane & 7);
    const int b_kof = ((lane >> 3) & 1) * 8;

    const bool pA0 = (m0 + a_r0) < M;
    const bool pA1 = (m0 + a_r0 + 64) < M;
    const uint32_t aOff0 = (uint32_t)(a_r0 * LDA + a_kc) * 2u;
    const uint32_t aOff1 = (uint32_t)((a_r0 + 64) * LDA + a_kc) * 2u;
    const uint32_t bOff = (uint32_t)(b_r * LDA + b_kc) * 2u;
    const __half* gA0 = A + (pA0 ? (long)(m0 + a_r0) * K + a_kc : 0);
    const __half* gA1 = A + (pA1 ? (long)(m0 + a_r0 + 64) * K + a_kc : 0);
    const __half* gBh = Bh + (long)(n0 + b_r) * K + b_kc;
    const __half* gBl = Bl + (long)(n0 + b_r) * K + b_kc;

#define LOAD_STAGE(st, k0)                           \
    do {                                             \
        cp16(aB[st] + aOff0, gA0 + (k0), pA0);       \
        cp16(aB[st] + aOff1, gA1 + (k0), pA1);       \
        cp16(bB[st][0] + bOff, gBh + (k0), true);    \
        cp16(bB[st][1] + bOff, gBl + (k0), true);    \
        cp_commit();                                 \
    } while (0)

    LOAD_STAGE(0, 0);

#pragma unroll
    for (int kt = 0; kt < T; kt++) {
        if (kt + 1 < T) {
            LOAD_STAGE((kt + 1) & 1, (kt + 1) * 32);
            cp_wait<1>();
        } else {
            cp_wait<0>();
        }
        __syncthreads();

        const int st = kt & 1;
#pragma unroll
        for (int ks = 0; ks < 32; ks += 16) {
            uint32_t fa[2][4], fbh[2][4], fbl[2][4];
#pragma unroll
            for (int mt = 0; mt < 2; mt++) {
                uint32_t off = (uint32_t)((wm * 32 + mt * 16 + a_row) * LDA + ks + a_kof) * 2u;
                ldm_x4(aB[st] + off, fa[mt]);
            }
#pragma unroll
            for (int np = 0; np < 2; np++) {
                uint32_t off = (uint32_t)((wn * 32 + np * 16 + b_row) * LDA + ks + b_kof) * 2u;
                ldm_x4(bB[st][0] + off, fbh[np]);
                ldm_x4(bB[st][1] + off, fbl[np]);
            }
#pragma unroll
            for (int term = 0; term < 2; term++) {
#pragma unroll
                for (int mt = 0; mt < 2; mt++) {
#pragma unroll
                    for (int nt = 0; nt < 4; nt++) {
                        uint32_t b0, b1;
                        if (term == 0) {
                            b0 = fbh[nt >> 1][(nt & 1) * 2];
                            b1 = fbh[nt >> 1][(nt & 1) * 2 + 1];
                        } else {
                            b0 = fbl[nt >> 1][(nt & 1) * 2];
                            b1 = fbl[nt >> 1][(nt & 1) * 2 + 1];
                        }
                        mma_f16(acc[mt][nt], fa[mt], b0, b1);
                    }
                }
            }
        }
        __syncthreads();
    }
#undef LOAD_STAGE

#pragma unroll
    for (int mt = 0; mt < 2; mt++) {
#pragma unroll
        for (int nt = 0; nt < 4; nt++) {
            int rbase = m0 + wm * 32 + mt * 16 + (lane >> 2);
            int col = n0 + wn * 32 + nt * 8 + (lane & 3) * 2;
            float* c = acc[mt][nt];
#pragma unroll
            for (int half = 0; half < 2; half++) {
                int row = rbase + half * 8;
                if (row >= M) continue;
                float v0 = c[half * 2], v1 = c[half * 2 + 1];
                if (EPI == 4 && n0 < 256) {
                    long base = (long)row * 256 + col;
                    *reinterpret_cast<__half2*>(&Out16[base]) =
                        __floats2half2_rn(sp_(v0), sp_(v1));
                } else if (EPI == 4) {
                    long base = (long)row * HD + (col - 256);
                    *reinterpret_cast<__half2*>(&Out2[base]) =
                        __floats2half2_rn(sigm_(v0), sigm_(v1));
                } else if (EPI == 2) {
                    long base = (long)row * HD + col;
                    float2 g2 = __half22float2(
                        *reinterpret_cast<const __half2*>(&Gb16[base]));
                    *reinterpret_cast<__half2*>(&Out16[base]) =
                        __floats2half2_rn(g2.x * sp_(v0), g2.y * sp_(v1));
                } else {  // EPI == 3
                    int seg = gidx[row];
                    atomicAdd(reinterpret_cast<float2*>(&Cf[(long)seg * HD + col]),
                              make_float2(v0, v1));
                }
            }
        }
    }
}

// ---- CSR gather + fused node update ----
__global__ void __launch_bounds__(256) k_gather() {
    int warp = (blockIdx.x * 256 + threadIdx.x) >> 5;
    int lane = threadIdx.x & 31;
    if (warp >= NN) return;
    int beg = g_off[warp], end = g_off[warp + 1];

    float4 acc = make_float4(0.f, 0.f, 0.f, 0.f);
    int e = beg;
    for (; e + 1 < end; e += 2) {
        int s0 = g_elist[e], s1 = g_elist[e + 1];
        float2 p0 = *reinterpret_cast<const float2*>(&g_M[(long)s0 * HD + lane * 4]);
        float2 p1 = *reinterpret_cast<const float2*>(&g_M[(long)s1 * HD + lane * 4]);
        const __half2* h0 = reinterpret_cast<const __half2*>(&p0);
        const __half2* h1 = reinterpret_cast<const __half2*>(&p1);
        float2 a0 = __half22float2(h0[0]), b0 = __half22float2(h0[1]);
        float2 a1 = __half22float2(h1[0]), b1 = __half22float2(h1[1]);
        acc.x += a0.x + a1.x;
        acc.y += a0.y + a1.y;
        acc.z += b0.x + b1.x;
        acc.w += b0.y + b1.y;
    }
    if (e < end) {
        int s0 = g_elist[e];
        float2 p0 = *reinterpret_cast<const float2*>(&g_M[(long)s0 * HD + lane * 4]);
        const __half2* h0 = reinterpret_cast<const __half2*>(&p0);
        float2 a0 = __half22float2(h0[0]), b0 = __half22float2(h0[1]);
        acc.x += a0.x;
        acc.y += a0.y;
        acc.z += b0.x;
        acc.w += b0.y;
    }

    int i4 = warp * 32 + lane;
    float4 x = ((float4*)g_x)[i4];
    x.x += sp_(acc.x);
    x.y += sp_(acc.y);
    x.z += sp_(acc.z);
    x.w += sp_(acc.w);
    ((float4*)g_x)[i4] = x;
    ((__half2*)g_xf)[i4 * 2] = __floats2half2_rn(x.x, x.y);
    ((__half2*)g_xf)[i4 * 2 + 1] = __floats2half2_rn(x.z, x.w);
}

__global__ void k_mlp(const float* __restrict__ counts,
                      const float* __restrict__ Wfc1, const float* __restrict__ bfc1,
                      const float* __restrict__ Wfc2, const float* __restrict__ bfc2,
                      const float* __restrict__ Wr, const float* __restrict__ br,
                      float* __restrict__ out) {
    __shared__ float s0[HD];
    __shared__ float s1[HD];
    __shared__ float red[HD];
    int g = blockIdx.x, t = threadIdx.x;

    float yv = g_y[g * HD + t] / counts[g];
    s0[t] = sp_(yv);
    __syncthreads();

    float acc = bfc1[t];
#pragma unroll 8
    for (int k = 0; k < HD; k++) acc += s0[k] * Wfc1[k * HD + t];
    s1[t] = sp_(acc);
    __syncthreads();

    acc = bfc2[t];
#pragma unroll 8
    for (int k = 0; k < HD; k++) acc += s1[k] * Wfc2[k * HD + t];
    float h2 = sp_(acc);

    red[t] = h2 * Wr[t];
    __syncthreads();
    for (int s = HD / 2; s > 0; s >>= 1) {
        if (t < s) red[t] += red[t + s];
        __syncthreads();
    }
    if (t == 0) out[g] = red[0] + br[0];
}

extern "C" void kernel_launch(void* const* d_in, const int* in_sizes, int n_in,
                              void* d_out, int out_size) {
    const int* nodes = (const int*)d_in[0];
    const int* esrc = (const int*)d_in[1];
    const int* etgt = (const int*)d_in[2];
    const int* gidx = (const int*)d_in[3];
    const float* counts = (const float*)d_in[4];
    const float* embed = (const float*)d_in[5];
    const float* Wg = (const float*)d_in[6];
    const float* We1 = (const float*)d_in[7];
    const float* We2 = (const float*)d_in[8];
    const float* Wp = (const float*)d_in[9];
    const float* Wfc1 = (const float*)d_in[10];
    const float* bfc1 = (const float*)d_in[11];
    const float* Wfc2 = (const float*)d_in[12];
    const float* bfc2 = (const float*)d_in[13];
    const float* Wr = (const float*)d_in[14];
    const float* br = (const float*)d_in[15];
    float* out = (float*)d_out;

    __half *pxf, *pAf, *pWfh, *pWfl, *psG, *pM;
    float* py;
    cudaGetSymbolAddress((void**)&pxf, g_xf);
    cudaGetSymbolAddress((void**)&pAf, g_Af);
    cudaGetSymbolAddress((void**)&pWfh, g_Wfh);
    cudaGetSymbolAddress((void**)&pWfl, g_Wfl);
    cudaGetSymbolAddress((void**)&psG, g_sG);
    cudaGetSymbolAddress((void**)&pM, g_M);
    cudaGetSymbolAddress((void**)&py, g_y);

    const int blocksM = (NN + 127) / 128;

    k_wsplit_all<<<(262144 + 255) / 256, 256>>>(Wg, We1, We2, Wp);
    k_zero_misc<<<(NN + 255) / 256, 256>>>();
    k_hist<<<(NE + 255) / 256, 256>>>(etgt);
    k_scan1<<<NB_SCAN, 1024>>>();
    k_scan2<<<1, 128>>>();
    k_scan3<<<(NN + 1023) / 1024, 1024>>>();
    k_fill<<<(NE + 255) / 256, 256>>>(esrc, etgt);
    {
        int n = NN * (HD / 4);
        k_embed<<<(n + 255) / 256, 256>>>(nodes, embed);
    }
    for (int i = 0; i < NCONV; i++) {
        k_g16<4, 384, HD><<<dim3(384 / 64, blocksM), 256>>>(
            pxf, pWfh + WCAT(i), pWfl + WCAT(i),
            nullptr, nullptr, nullptr, pAf, psG, NN);
        k_g16<2, HD, EF><<<dim3(HD / 64, blocksM), 256>>>(
            pAf, pWfh + WE2(i), pWfl + WE2(i),
            nullptr, psG, nullptr, pM, nullptr, NN);
        k_gather<<<(NN + 7) / 8, 256>>>();
    }
    k_g16<3, HD, HD><<<dim3(HD / 64, blocksM), 256>>>(
        pxf, pWfh + WPT, pWfl + WPT,
        py, nullptr, gidx, nullptr, nullptr, NN);
    k_mlp<<<NG, HD>>>(counts, Wfc1, bfc1, Wfc2, bfc2, Wr, br, out);
}